// round 2
// baseline (speedup 1.0000x reference)
#include <cuda_runtime.h>
#include <cstdint>
#include <cstddef>

#define NBATCH 32
#define NNODE  512
#define NTIME  12
#define NCH    64
#define NM     (NTIME * NCH)            /* 768 */
#define NROWS  (NBATCH * NNODE * NTIME) /* 196608 */

/* ------------------------------------------------------------------ */
/* Device scratch (no allocations allowed)                             */
/* ------------------------------------------------------------------ */
__device__ float g_SW1[40 * 20];
__device__ float g_SW2[40 * 20];
__device__ float g_e1[NNODE * 20];
__device__ float g_e2[NNODE * 20];
__device__ float g_A[NNODE * NNODE];
__device__ float g_dinv[NNODE];
__device__ float g_Ls[NNODE * NNODE];
__device__ float g_T2[NNODE * NNODE];
__device__ float g_T3[NNODE * NNODE];
__device__ float g_Wid[64 * 64];
__device__ float g_y1[(size_t)NBATCH * NNODE * NM];
__device__ float g_y2[(size_t)NBATCH * NNODE * NM];

/* ------------------------------------------------------------------ */
/* f32x2 packed-FMA helpers (Blackwell FFMA2, 2x fp32 rate)            */
/* ------------------------------------------------------------------ */
__device__ __forceinline__ unsigned long long pack2(float a) {
    unsigned long long r;
    asm("mov.b64 %0, {%1, %1};" : "=l"(r) : "f"(a));
    return r;
}
__device__ __forceinline__ void fma2(unsigned long long& acc,
                                     unsigned long long a,
                                     unsigned long long b) {
    asm("fma.rn.f32x2 %0, %1, %2, %0;" : "+l"(acc) : "l"(a), "l"(b));
}
__device__ __forceinline__ float2 unpack2(unsigned long long v) {
    float2 r;
    asm("mov.b64 {%0, %1}, %2;" : "=f"(r.x), "=f"(r.y) : "l"(v));
    return r;
}

/* ------------------------------------------------------------------ */
/* Phase A: adaptive adjacency -> Ls, T2, T3                           */
/* ------------------------------------------------------------------ */
__global__ void k_softmax(const float* __restrict__ W1,
                          const float* __restrict__ W2) {
    int j = threadIdx.x;
    if (j >= 40) return;
    const float* W = (j < 20) ? W1 : W2;
    float* S = (j < 20) ? g_SW1 : g_SW2;
    int col = (j < 20) ? j : (j - 20);
    float mx = -1e30f;
    for (int k = 0; k < 40; k++) mx = fmaxf(mx, W[k * 20 + col]);
    float s = 0.f;
    for (int k = 0; k < 40; k++) s += expf(W[k * 20 + col] - mx);
    float inv = 1.f / s;
    for (int k = 0; k < 40; k++) S[k * 20 + col] = expf(W[k * 20 + col] - mx) * inv;
}

__global__ void k_embed(const float* __restrict__ emb) {
    int row = blockIdx.x;
    int lane = threadIdx.x;
    float v1 = 0.f, v2 = 0.f;
    if (lane < 20) {
        for (int k = 0; k < 40; k++) {
            float e = emb[row * 40 + k];
            v1 += e * g_SW1[k * 20 + lane];
            v2 += e * g_SW2[k * 20 + lane];
        }
    }
    float n1 = v1 * v1, n2 = v2 * v2;
    for (int off = 16; off; off >>= 1) {
        n1 += __shfl_xor_sync(0xFFFFFFFFu, n1, off);
        n2 += __shfl_xor_sync(0xFFFFFFFFu, n2, off);
    }
    if (lane < 20) {
        g_e1[row * 20 + lane] = v1 / (sqrtf(n1) + 1e-8f);
        g_e2[row * 20 + lane] = v2 / (sqrtf(n2) + 1e-8f);
    }
}

__global__ void k_buildA(const float* __restrict__ adj) {
    int v = blockIdx.x;
    __shared__ float e1v[20];
    __shared__ float red[256];
    if (threadIdx.x < 20) e1v[threadIdx.x] = g_e1[v * 20 + threadIdx.x];
    __syncthreads();
    float sum = 0.f;
    for (int w = threadIdx.x; w < NNODE; w += 256) {
        float ad = adj[v * NNODE + w];
        float val = 9e-15f;
        if (ad > 0.f) {
            float dot = 0.f;
#pragma unroll
            for (int k = 0; k < 20; k++) dot += e1v[k] * g_e2[w * 20 + k];
            val = dot + ad;
        }
        g_A[v * NNODE + w] = val;
        sum += val;
    }
    red[threadIdx.x] = sum;
    __syncthreads();
    for (int s = 128; s; s >>= 1) {
        if (threadIdx.x < s) red[threadIdx.x] += red[threadIdx.x + s];
        __syncthreads();
    }
    if (threadIdx.x == 0) g_dinv[v] = 1.0f / sqrtf(red[0]);
}

__global__ void k_Ls() {
    int v = blockIdx.x;
    float dv = g_dinv[v];
    for (int w = threadIdx.x; w < NNODE; w += 256)
        g_Ls[v * NNODE + w] = -dv * g_A[v * NNODE + w] * g_dinv[w];
}

/* C = 2*A@B - (D ? D : I), all 512x512 fp32 row-major */
__global__ void k_gemm512(const float* __restrict__ A,
                          const float* __restrict__ B,
                          const float* __restrict__ D,
                          float* __restrict__ C) {
    __shared__ float As[16][68];
    __shared__ float Bs[16][68];
    const int tx = threadIdx.x, ty = threadIdx.y;
    const int t = ty * 16 + tx;
    const int i0 = blockIdx.y * 64, j0 = blockIdx.x * 64;
    float acc[4][4] = {};
    for (int k0 = 0; k0 < NNODE; k0 += 16) {
#pragma unroll
        for (int r = 0; r < 4; r++) {
            int idx = t + r * 256;
            int ia = idx >> 4, ka = idx & 15;
            As[ka][ia] = A[(size_t)(i0 + ia) * NNODE + k0 + ka];
            int kb = idx >> 6, jb = idx & 63;
            Bs[kb][jb] = B[(size_t)(k0 + kb) * NNODE + j0 + jb];
        }
        __syncthreads();
#pragma unroll
        for (int k = 0; k < 16; k++) {
            float av[4], bv[4];
#pragma unroll
            for (int i = 0; i < 4; i++) av[i] = As[k][ty * 4 + i];
#pragma unroll
            for (int j = 0; j < 4; j++) bv[j] = Bs[k][tx * 4 + j];
#pragma unroll
            for (int i = 0; i < 4; i++)
#pragma unroll
                for (int j = 0; j < 4; j++) acc[i][j] = fmaf(av[i], bv[j], acc[i][j]);
        }
        __syncthreads();
    }
#pragma unroll
    for (int i = 0; i < 4; i++)
#pragma unroll
        for (int j = 0; j < 4; j++) {
            int gi = i0 + ty * 4 + i, gj = j0 + tx * 4 + j;
            float sub = D ? D[(size_t)gi * NNODE + gj] : (gi == gj ? 1.f : 0.f);
            C[(size_t)gi * NNODE + gj] = 2.f * acc[i][j] - sub;
        }
}

__global__ void k_wid(const float* __restrict__ mlpw) {
    int i = blockIdx.x * 256 + threadIdx.x; /* < 4096 */
    int o = i >> 6, c = i & 63;
    g_Wid[i] = mlpw[o * 832 + c] + mlpw[o * 832 + 64 + c] +
               mlpw[o * 832 + 128 + c] + mlpw[o * 832 + 192 + c];
}

/* ------------------------------------------------------------------ */
/* Node GEMM: Y[b][w][m] = sum_v Aop[v][w] * X[b][v][m]                */
/* X,Y: (32, 512, 768)  Aop: (512, 512)                                */
/* BM=128(w) BN=128(m) BK=16, 256 thr, 8x8 microtile, f32x2 FMA        */
/* ------------------------------------------------------------------ */
__global__ void __launch_bounds__(256, 2) k_node_gemm(
    const float* __restrict__ X, const float* __restrict__ Aop,
    float* __restrict__ Y) {
    __shared__ float As[2][16][128];
    __shared__ float Xs[2][16][128];

    const int b  = blockIdx.z;
    const int w0 = blockIdx.y * 128;
    const int m0 = blockIdx.x * 128;
    const float* Xb = X + (size_t)b * (NNODE * NM) + m0;
    float* Yb = Y + (size_t)b * (NNODE * NM) + m0;

    const int t  = threadIdx.x;
    const int tx = t & 15;
    const int ty = t >> 4;

    const int ka0 = t >> 5;
    const int qa0 = t & 31;
    const int ka1 = (t + 256) >> 5;
    const int qa1 = (t + 256) & 31;

    unsigned long long acc[8][4];
#pragma unroll
    for (int i = 0; i < 8; i++)
#pragma unroll
        for (int j = 0; j < 4; j++) acc[i][j] = 0ULL;

    /* prologue: tile k0=0 -> buf 0 */
    {
        float4 a0 = *(const float4*)(Aop + (size_t)ka0 * NNODE + w0 + qa0 * 4);
        float4 a1 = *(const float4*)(Aop + (size_t)ka1 * NNODE + w0 + qa1 * 4);
        float4 x0 = *(const float4*)(Xb + (size_t)ka0 * NM + qa0 * 4);
        float4 x1 = *(const float4*)(Xb + (size_t)ka1 * NM + qa1 * 4);
        *(float4*)(&As[0][ka0][qa0 * 4]) = a0;
        *(float4*)(&As[0][ka1][qa1 * 4]) = a1;
        *(float4*)(&Xs[0][ka0][qa0 * 4]) = x0;
        *(float4*)(&Xs[0][ka1][qa1 * 4]) = x1;
    }
    __syncthreads();

    int buf = 0;
    for (int k0 = 0; k0 < NNODE; k0 += 16) {
        float4 a0, a1, x0, x1;
        const bool more = (k0 + 16) < NNODE;
        if (more) {
            const int kb = k0 + 16;
            a0 = *(const float4*)(Aop + (size_t)(kb + ka0) * NNODE + w0 + qa0 * 4);
            a1 = *(const float4*)(Aop + (size_t)(kb + ka1) * NNODE + w0 + qa1 * 4);
            x0 = *(const float4*)(Xb + (size_t)(kb + ka0) * NM + qa0 * 4);
            x1 = *(const float4*)(Xb + (size_t)(kb + ka1) * NM + qa1 * 4);
        }
#pragma unroll
        for (int k = 0; k < 16; k++) {
            float4 av0 = *(const float4*)(&As[buf][k][tx * 8]);
            float4 av1 = *(const float4*)(&As[buf][k][tx * 8 + 4]);
            ulonglong2 xv0 = *(const ulonglong2*)(&Xs[buf][k][ty * 8]);
            ulonglong2 xv1 = *(const ulonglong2*)(&Xs[buf][k][ty * 8 + 4]);
            unsigned long long xp[4] = {xv0.x, xv0.y, xv1.x, xv1.y};
            float aarr[8] = {av0.x, av0.y, av0.z, av0.w,
                             av1.x, av1.y, av1.z, av1.w};
#pragma unroll
            for (int i = 0; i < 8; i++) {
                unsigned long long a2 = pack2(aarr[i]);
#pragma unroll
                for (int j = 0; j < 4; j++) fma2(acc[i][j], a2, xp[j]);
            }
        }
        if (more) {
            *(float4*)(&As[buf ^ 1][ka0][qa0 * 4]) = a0;
            *(float4*)(&As[buf ^ 1][ka1][qa1 * 4]) = a1;
            *(float4*)(&Xs[buf ^ 1][ka0][qa0 * 4]) = x0;
            *(float4*)(&Xs[buf ^ 1][ka1][qa1 * 4]) = x1;
        }
        __syncthreads();
        buf ^= 1;
    }

#pragma unroll
    for (int i = 0; i < 8; i++) {
        float* yr = Yb + (size_t)(w0 + tx * 8 + i) * NM + ty * 8;
#pragma unroll
        for (int j = 0; j < 4; j++) {
            float2 v = unpack2(acc[i][j]);
            *(float2*)(yr + 2 * j) = v;
        }
    }
}

/* ------------------------------------------------------------------ */
/* Channel mix: out[r][o] (+)= sum_c Yv[r][c] * W[o*wstride + c]       */
/* r = (b*512+w)*12+t, 64 rows per block                               */
/* ------------------------------------------------------------------ */
__global__ void __launch_bounds__(256) k_chanmix(
    const float* __restrict__ Yv, const float* __restrict__ W, int wstride,
    float* __restrict__ out, int accumulate) {
    __shared__ float Ws[64][64]; /* [c][o] */
    __shared__ float Ys[64][68];
    const int t = threadIdx.x;
    const size_t r0 = (size_t)blockIdx.x * 64;
    for (int i = t; i < 4096; i += 256) {
        int o = i >> 6, c = i & 63;
        Ws[c][o] = W[(size_t)o * wstride + c];
    }
    for (int i = t; i < 1024; i += 256) {
        int row = i >> 4, c4 = (i & 15) * 4;
        float4 v = *(const float4*)(Yv + (r0 + row) * 64 + c4);
        Ys[row][c4 + 0] = v.x;
        Ys[row][c4 + 1] = v.y;
        Ys[row][c4 + 2] = v.z;
        Ys[row][c4 + 3] = v.w;
    }
    __syncthreads();
    const int tx = t & 15, ty = t >> 4;
    float acc[4][4] = {};
#pragma unroll
    for (int c = 0; c < 64; c++) {
        float yv[4], wv[4];
#pragma unroll
        for (int i = 0; i < 4; i++) yv[i] = Ys[ty * 4 + i][c];
#pragma unroll
        for (int j = 0; j < 4; j++) wv[j] = Ws[c][tx * 4 + j];
#pragma unroll
        for (int i = 0; i < 4; i++)
#pragma unroll
            for (int j = 0; j < 4; j++) acc[i][j] = fmaf(yv[i], wv[j], acc[i][j]);
    }
#pragma unroll
    for (int i = 0; i < 4; i++) {
        float* po = out + (r0 + ty * 4 + i) * 64 + tx * 4;
        float4 v;
        if (accumulate) v = *(float4*)po;
        else v = make_float4(0.f, 0.f, 0.f, 0.f);
        v.x += acc[i][0];
        v.y += acc[i][1];
        v.z += acc[i][2];
        v.w += acc[i][3];
        *(float4*)po = v;
    }
}

/* out = relu(out + bias[o] + x), vectorized float4 */
__global__ void k_final(const float* __restrict__ x,
                        const float* __restrict__ bias,
                        float* __restrict__ out) {
    const size_t i = (size_t)blockIdx.x * 256 + threadIdx.x;
    const float4* x4 = (const float4*)x;
    float4* o4 = (float4*)out;
    const float4* b4 = (const float4*)bias;
    float4 xo = x4[i];
    float4 a = o4[i];
    float4 bb = b4[i & 15];
    a.x = fmaxf(a.x + bb.x + xo.x, 0.f);
    a.y = fmaxf(a.y + bb.y + xo.y, 0.f);
    a.z = fmaxf(a.z + bb.z + xo.z, 0.f);
    a.w = fmaxf(a.w + bb.w + xo.w, 0.f);
    o4[i] = a;
}

/* ------------------------------------------------------------------ */
extern "C" void kernel_launch(void* const* d_in, const int* in_sizes, int n_in,
                              void* d_out, int out_size) {
    (void)in_sizes; (void)n_in; (void)out_size;
    const float* x    = (const float*)d_in[0];
    const float* adj  = (const float*)d_in[1];
    const float* emb  = (const float*)d_in[2];
    const float* W1   = (const float*)d_in[3];
    const float* W2   = (const float*)d_in[4];
    const float* mlpw = (const float*)d_in[5];
    const float* mlpb = (const float*)d_in[6];
    float* out = (float*)d_out;

    float *pLs, *pT2, *pT3, *pWid, *py1, *py2;
    cudaGetSymbolAddress((void**)&pLs, g_Ls);
    cudaGetSymbolAddress((void**)&pT2, g_T2);
    cudaGetSymbolAddress((void**)&pT3, g_T3);
    cudaGetSymbolAddress((void**)&pWid, g_Wid);
    cudaGetSymbolAddress((void**)&py1, g_y1);
    cudaGetSymbolAddress((void**)&py2, g_y2);

    /* Phase A: supports */
    k_softmax<<<1, 64>>>(W1, W2);
    k_embed<<<512, 32>>>(emb);
    k_buildA<<<512, 256>>>(adj);
    k_Ls<<<512, 256>>>();
    dim3 g512(8, 8), b512(16, 16);
    k_gemm512<<<g512, b512>>>(pLs, pLs, (const float*)nullptr, pT2); /* T2 = 2Ls^2 - I  */
    k_gemm512<<<g512, b512>>>(pLs, pT2, pLs, pT3);                   /* T3 = 2Ls*T2 - Ls */
    k_wid<<<16, 256>>>(mlpw);

    /* identity blocks (j=0..3) collapsed into one channel mix of x */
    k_chanmix<<<NROWS / 64, 256>>>(x, pWid, 64, out, 0);

    /* 3 support chains x 3 hops */
    const float* aops[3] = {pLs, pT2, pT3};
    const int j0s[3] = {4, 7, 10};
    dim3 gn(6, 4, 32);
    for (int s = 0; s < 3; s++) {
        const float* a = aops[s];
        int j0 = j0s[s];
        k_node_gemm<<<gn, 256>>>(x, a, py1);
        k_chanmix<<<NROWS / 64, 256>>>(py1, mlpw + (size_t)j0 * 64, 832, out, 1);
        k_node_gemm<<<gn, 256>>>(py1, a, py2);
        k_chanmix<<<NROWS / 64, 256>>>(py2, mlpw + (size_t)(j0 + 1) * 64, 832, out, 1);
        k_node_gemm<<<gn, 256>>>(py2, a, py1);
        k_chanmix<<<NROWS / 64, 256>>>(py1, mlpw + (size_t)(j0 + 2) * 64, 832, out, 1);
    }

    /* residual + bias + relu */
    k_final<<<(NROWS * NCH) / (4 * 256), 256>>>(x, mlpb, out);
}

// round 3
// speedup vs baseline: 1.0008x; 1.0008x over previous
#include <cuda_runtime.h>
#include <cstdint>
#include <cstddef>

#define NBATCH 32
#define NNODE  512
#define NTIME  12
#define NCH    64
#define NM     (NTIME * NCH)            /* 768 */
#define NROWS  (NBATCH * NNODE * NTIME) /* 196608 */

/* ------------------------------------------------------------------ */
/* Device scratch (no allocations allowed)                             */
/* ------------------------------------------------------------------ */
__device__ float g_SW1[40 * 20];
__device__ float g_SW2[40 * 20];
__device__ float g_e1[NNODE * 20];
__device__ float g_e2[NNODE * 20];
__device__ float g_A[NNODE * NNODE];
__device__ float g_dinv[NNODE];
__device__ float g_Ls[NNODE * NNODE];
__device__ float g_T2[NNODE * NNODE];
__device__ float g_T3[NNODE * NNODE];
__device__ float g_Wid[64 * 64];
__device__ float g_y1[(size_t)NBATCH * NNODE * NM];
__device__ float g_y2[(size_t)NBATCH * NNODE * NM];

/* ------------------------------------------------------------------ */
/* f32x2 packed-FMA helpers (Blackwell FFMA2, 2x fp32 rate)            */
/* ------------------------------------------------------------------ */
__device__ __forceinline__ unsigned long long pack2(float a) {
    unsigned long long r;
    asm("mov.b64 %0, {%1, %1};" : "=l"(r) : "f"(a));
    return r;
}
__device__ __forceinline__ void fma2(unsigned long long& acc,
                                     unsigned long long a,
                                     unsigned long long b) {
    asm("fma.rn.f32x2 %0, %1, %2, %0;" : "+l"(acc) : "l"(a), "l"(b));
}
__device__ __forceinline__ float2 unpack2(unsigned long long v) {
    float2 r;
    asm("mov.b64 {%0, %1}, %2;" : "=f"(r.x), "=f"(r.y) : "l"(v));
    return r;
}

/* ------------------------------------------------------------------ */
/* Phase A: adaptive adjacency -> Ls, T2, T3                           */
/* ------------------------------------------------------------------ */
__global__ void k_softmax(const float* __restrict__ W1,
                          const float* __restrict__ W2) {
    int j = threadIdx.x;
    if (j >= 40) return;
    const float* W = (j < 20) ? W1 : W2;
    float* S = (j < 20) ? g_SW1 : g_SW2;
    int col = (j < 20) ? j : (j - 20);
    float mx = -1e30f;
    for (int k = 0; k < 40; k++) mx = fmaxf(mx, W[k * 20 + col]);
    float s = 0.f;
    for (int k = 0; k < 40; k++) s += expf(W[k * 20 + col] - mx);
    float inv = 1.f / s;
    for (int k = 0; k < 40; k++) S[k * 20 + col] = expf(W[k * 20 + col] - mx) * inv;
}

__global__ void k_embed(const float* __restrict__ emb) {
    int row = blockIdx.x;
    int lane = threadIdx.x;
    float v1 = 0.f, v2 = 0.f;
    if (lane < 20) {
        for (int k = 0; k < 40; k++) {
            float e = emb[row * 40 + k];
            v1 += e * g_SW1[k * 20 + lane];
            v2 += e * g_SW2[k * 20 + lane];
        }
    }
    float n1 = v1 * v1, n2 = v2 * v2;
    for (int off = 16; off; off >>= 1) {
        n1 += __shfl_xor_sync(0xFFFFFFFFu, n1, off);
        n2 += __shfl_xor_sync(0xFFFFFFFFu, n2, off);
    }
    if (lane < 20) {
        g_e1[row * 20 + lane] = v1 / (sqrtf(n1) + 1e-8f);
        g_e2[row * 20 + lane] = v2 / (sqrtf(n2) + 1e-8f);
    }
}

__global__ void k_buildA(const float* __restrict__ adj) {
    int v = blockIdx.x;
    __shared__ float e1v[20];
    __shared__ float red[256];
    if (threadIdx.x < 20) e1v[threadIdx.x] = g_e1[v * 20 + threadIdx.x];
    __syncthreads();
    float sum = 0.f;
    for (int w = threadIdx.x; w < NNODE; w += 256) {
        float ad = adj[v * NNODE + w];
        float val = 9e-15f;
        if (ad > 0.f) {
            float dot = 0.f;
#pragma unroll
            for (int k = 0; k < 20; k++) dot += e1v[k] * g_e2[w * 20 + k];
            val = dot + ad;
        }
        g_A[v * NNODE + w] = val;
        sum += val;
    }
    red[threadIdx.x] = sum;
    __syncthreads();
    for (int s = 128; s; s >>= 1) {
        if (threadIdx.x < s) red[threadIdx.x] += red[threadIdx.x + s];
        __syncthreads();
    }
    if (threadIdx.x == 0) g_dinv[v] = 1.0f / sqrtf(red[0]);
}

__global__ void k_Ls() {
    int v = blockIdx.x;
    float dv = g_dinv[v];
    for (int w = threadIdx.x; w < NNODE; w += 256)
        g_Ls[v * NNODE + w] = -dv * g_A[v * NNODE + w] * g_dinv[w];
}

/* C = 2*A@B - (D ? D : I), all 512x512 fp32 row-major */
__global__ void k_gemm512(const float* __restrict__ A,
                          const float* __restrict__ B,
                          const float* __restrict__ D,
                          float* __restrict__ C) {
    __shared__ float As[16][68];
    __shared__ float Bs[16][68];
    const int tx = threadIdx.x, ty = threadIdx.y;
    const int t = ty * 16 + tx;
    const int i0 = blockIdx.y * 64, j0 = blockIdx.x * 64;
    float acc[4][4] = {};
    for (int k0 = 0; k0 < NNODE; k0 += 16) {
#pragma unroll
        for (int r = 0; r < 4; r++) {
            int idx = t + r * 256;
            int ia = idx >> 4, ka = idx & 15;
            As[ka][ia] = A[(size_t)(i0 + ia) * NNODE + k0 + ka];
            int kb = idx >> 6, jb = idx & 63;
            Bs[kb][jb] = B[(size_t)(k0 + kb) * NNODE + j0 + jb];
        }
        __syncthreads();
#pragma unroll
        for (int k = 0; k < 16; k++) {
            float av[4], bv[4];
#pragma unroll
            for (int i = 0; i < 4; i++) av[i] = As[k][ty * 4 + i];
#pragma unroll
            for (int j = 0; j < 4; j++) bv[j] = Bs[k][tx * 4 + j];
#pragma unroll
            for (int i = 0; i < 4; i++)
#pragma unroll
                for (int j = 0; j < 4; j++) acc[i][j] = fmaf(av[i], bv[j], acc[i][j]);
        }
        __syncthreads();
    }
#pragma unroll
    for (int i = 0; i < 4; i++)
#pragma unroll
        for (int j = 0; j < 4; j++) {
            int gi = i0 + ty * 4 + i, gj = j0 + tx * 4 + j;
            float sub = D ? D[(size_t)gi * NNODE + gj] : (gi == gj ? 1.f : 0.f);
            C[(size_t)gi * NNODE + gj] = 2.f * acc[i][j] - sub;
        }
}

__global__ void k_wid(const float* __restrict__ mlpw) {
    int i = blockIdx.x * 256 + threadIdx.x; /* < 4096 */
    int o = i >> 6, c = i & 63;
    g_Wid[i] = mlpw[o * 832 + c] + mlpw[o * 832 + 64 + c] +
               mlpw[o * 832 + 128 + c] + mlpw[o * 832 + 192 + c];
}

/* ------------------------------------------------------------------ */
/* Node GEMM: Y[b][w][m] = sum_v Aop[v][w] * X[b][v][m]                */
/* X,Y: (32, 512, 768)  Aop: (512, 512)                                */
/* BM=128(w) BN=128(m) BK=16, 256 thr, 8x8 microtile, f32x2 FMA        */
/* ------------------------------------------------------------------ */
__global__ void __launch_bounds__(256, 2) k_node_gemm(
    const float* __restrict__ X, const float* __restrict__ Aop,
    float* __restrict__ Y) {
    __shared__ float As[2][16][128];
    __shared__ float Xs[2][16][128];

    const int b  = blockIdx.z;
    const int w0 = blockIdx.y * 128;
    const int m0 = blockIdx.x * 128;
    const float* Xb = X + (size_t)b * (NNODE * NM) + m0;
    float* Yb = Y + (size_t)b * (NNODE * NM) + m0;

    const int t  = threadIdx.x;
    const int tx = t & 15;
    const int ty = t >> 4;

    const int ka0 = t >> 5;
    const int qa0 = t & 31;
    const int ka1 = (t + 256) >> 5;
    const int qa1 = (t + 256) & 31;

    unsigned long long acc[8][4];
#pragma unroll
    for (int i = 0; i < 8; i++)
#pragma unroll
        for (int j = 0; j < 4; j++) acc[i][j] = 0ULL;

    /* prologue: tile k0=0 -> buf 0 */
    {
        float4 a0 = *(const float4*)(Aop + (size_t)ka0 * NNODE + w0 + qa0 * 4);
        float4 a1 = *(const float4*)(Aop + (size_t)ka1 * NNODE + w0 + qa1 * 4);
        float4 x0 = *(const float4*)(Xb + (size_t)ka0 * NM + qa0 * 4);
        float4 x1 = *(const float4*)(Xb + (size_t)ka1 * NM + qa1 * 4);
        *(float4*)(&As[0][ka0][qa0 * 4]) = a0;
        *(float4*)(&As[0][ka1][qa1 * 4]) = a1;
        *(float4*)(&Xs[0][ka0][qa0 * 4]) = x0;
        *(float4*)(&Xs[0][ka1][qa1 * 4]) = x1;
    }
    __syncthreads();

    int buf = 0;
    for (int k0 = 0; k0 < NNODE; k0 += 16) {
        float4 a0, a1, x0, x1;
        const bool more = (k0 + 16) < NNODE;
        if (more) {
            const int kb = k0 + 16;
            a0 = *(const float4*)(Aop + (size_t)(kb + ka0) * NNODE + w0 + qa0 * 4);
            a1 = *(const float4*)(Aop + (size_t)(kb + ka1) * NNODE + w0 + qa1 * 4);
            x0 = *(const float4*)(Xb + (size_t)(kb + ka0) * NM + qa0 * 4);
            x1 = *(const float4*)(Xb + (size_t)(kb + ka1) * NM + qa1 * 4);
        }
#pragma unroll
        for (int k = 0; k < 16; k++) {
            float4 av0 = *(const float4*)(&As[buf][k][tx * 8]);
            float4 av1 = *(const float4*)(&As[buf][k][tx * 8 + 4]);
            ulonglong2 xv0 = *(const ulonglong2*)(&Xs[buf][k][ty * 8]);
            ulonglong2 xv1 = *(const ulonglong2*)(&Xs[buf][k][ty * 8 + 4]);
            unsigned long long xp[4] = {xv0.x, xv0.y, xv1.x, xv1.y};
            float aarr[8] = {av0.x, av0.y, av0.z, av0.w,
                             av1.x, av1.y, av1.z, av1.w};
#pragma unroll
            for (int i = 0; i < 8; i++) {
                unsigned long long a2 = pack2(aarr[i]);
#pragma unroll
                for (int j = 0; j < 4; j++) fma2(acc[i][j], a2, xp[j]);
            }
        }
        if (more) {
            *(float4*)(&As[buf ^ 1][ka0][qa0 * 4]) = a0;
            *(float4*)(&As[buf ^ 1][ka1][qa1 * 4]) = a1;
            *(float4*)(&Xs[buf ^ 1][ka0][qa0 * 4]) = x0;
            *(float4*)(&Xs[buf ^ 1][ka1][qa1 * 4]) = x1;
        }
        __syncthreads();
        buf ^= 1;
    }

#pragma unroll
    for (int i = 0; i < 8; i++) {
        float* yr = Yb + (size_t)(w0 + tx * 8 + i) * NM + ty * 8;
#pragma unroll
        for (int j = 0; j < 4; j++) {
            float2 v = unpack2(acc[i][j]);
            *(float2*)(yr + 2 * j) = v;
        }
    }
}

/* ------------------------------------------------------------------ */
/* Channel mix: out[r][o] (+)= sum_c Yv[r][c] * W[o*wstride + c]       */
/* r = (b*512+w)*12+t, 64 rows per block                               */
/* ------------------------------------------------------------------ */
__global__ void __launch_bounds__(256) k_chanmix(
    const float* __restrict__ Yv, const float* __restrict__ W, int wstride,
    float* __restrict__ out, int accumulate) {
    __shared__ float Ws[64][64]; /* [c][o] */
    __shared__ float Ys[64][68];
    const int t = threadIdx.x;
    const size_t r0 = (size_t)blockIdx.x * 64;
    for (int i = t; i < 4096; i += 256) {
        int o = i >> 6, c = i & 63;
        Ws[c][o] = W[(size_t)o * wstride + c];
    }
    for (int i = t; i < 1024; i += 256) {
        int row = i >> 4, c4 = (i & 15) * 4;
        float4 v = *(const float4*)(Yv + (r0 + row) * 64 + c4);
        Ys[row][c4 + 0] = v.x;
        Ys[row][c4 + 1] = v.y;
        Ys[row][c4 + 2] = v.z;
        Ys[row][c4 + 3] = v.w;
    }
    __syncthreads();
    const int tx = t & 15, ty = t >> 4;
    float acc[4][4] = {};
#pragma unroll
    for (int c = 0; c < 64; c++) {
        float yv[4], wv[4];
#pragma unroll
        for (int i = 0; i < 4; i++) yv[i] = Ys[ty * 4 + i][c];
#pragma unroll
        for (int j = 0; j < 4; j++) wv[j] = Ws[c][tx * 4 + j];
#pragma unroll
        for (int i = 0; i < 4; i++)
#pragma unroll
            for (int j = 0; j < 4; j++) acc[i][j] = fmaf(yv[i], wv[j], acc[i][j]);
    }
#pragma unroll
    for (int i = 0; i < 4; i++) {
        float* po = out + (r0 + ty * 4 + i) * 64 + tx * 4;
        float4 v;
        if (accumulate) v = *(float4*)po;
        else v = make_float4(0.f, 0.f, 0.f, 0.f);
        v.x += acc[i][0];
        v.y += acc[i][1];
        v.z += acc[i][2];
        v.w += acc[i][3];
        *(float4*)po = v;
    }
}

/* out = relu(out + bias[o] + x), vectorized float4 */
__global__ void k_final(const float* __restrict__ x,
                        const float* __restrict__ bias,
                        float* __restrict__ out) {
    const size_t i = (size_t)blockIdx.x * 256 + threadIdx.x;
    const float4* x4 = (const float4*)x;
    float4* o4 = (float4*)out;
    const float4* b4 = (const float4*)bias;
    float4 xo = x4[i];
    float4 a = o4[i];
    float4 bb = b4[i & 15];
    a.x = fmaxf(a.x + bb.x + xo.x, 0.f);
    a.y = fmaxf(a.y + bb.y + xo.y, 0.f);
    a.z = fmaxf(a.z + bb.z + xo.z, 0.f);
    a.w = fmaxf(a.w + bb.w + xo.w, 0.f);
    o4[i] = a;
}

/* ------------------------------------------------------------------ */
extern "C" void kernel_launch(void* const* d_in, const int* in_sizes, int n_in,
                              void* d_out, int out_size) {
    (void)in_sizes; (void)n_in; (void)out_size;
    const float* x    = (const float*)d_in[0];
    const float* adj  = (const float*)d_in[1];
    const float* emb  = (const float*)d_in[2];
    const float* W1   = (const float*)d_in[3];
    const float* W2   = (const float*)d_in[4];
    const float* mlpw = (const float*)d_in[5];
    const float* mlpb = (const float*)d_in[6];
    float* out = (float*)d_out;

    float *pLs, *pT2, *pT3, *pWid, *py1, *py2;
    cudaGetSymbolAddress((void**)&pLs, g_Ls);
    cudaGetSymbolAddress((void**)&pT2, g_T2);
    cudaGetSymbolAddress((void**)&pT3, g_T3);
    cudaGetSymbolAddress((void**)&pWid, g_Wid);
    cudaGetSymbolAddress((void**)&py1, g_y1);
    cudaGetSymbolAddress((void**)&py2, g_y2);

    /* Phase A: supports */
    k_softmax<<<1, 64>>>(W1, W2);
    k_embed<<<512, 32>>>(emb);
    k_buildA<<<512, 256>>>(adj);
    k_Ls<<<512, 256>>>();
    dim3 g512(8, 8), b512(16, 16);
    k_gemm512<<<g512, b512>>>(pLs, pLs, (const float*)nullptr, pT2); /* T2 = 2Ls^2 - I  */
    k_gemm512<<<g512, b512>>>(pLs, pT2, pLs, pT3);                   /* T3 = 2Ls*T2 - Ls */
    k_wid<<<16, 256>>>(mlpw);

    /* identity blocks (j=0..3) collapsed into one channel mix of x */
    k_chanmix<<<NROWS / 64, 256>>>(x, pWid, 64, out, 0);

    /* 3 support chains x 3 hops */
    const float* aops[3] = {pLs, pT2, pT3};
    const int j0s[3] = {4, 7, 10};
    dim3 gn(6, 4, 32);
    for (int s = 0; s < 3; s++) {
        const float* a = aops[s];
        int j0 = j0s[s];
        k_node_gemm<<<gn, 256>>>(x, a, py1);
        k_chanmix<<<NROWS / 64, 256>>>(py1, mlpw + (size_t)j0 * 64, 832, out, 1);
        k_node_gemm<<<gn, 256>>>(py1, a, py2);
        k_chanmix<<<NROWS / 64, 256>>>(py2, mlpw + (size_t)(j0 + 1) * 64, 832, out, 1);
        k_node_gemm<<<gn, 256>>>(py2, a, py1);
        k_chanmix<<<NROWS / 64, 256>>>(py1, mlpw + (size_t)(j0 + 2) * 64, 832, out, 1);
    }

    /* residual + bias + relu */
    k_final<<<(NROWS * NCH) / (4 * 256), 256>>>(x, mlpb, out);
}

// round 5
// speedup vs baseline: 1.6134x; 1.6122x over previous
#include <cuda_runtime.h>
#include <cuda_bf16.h>
#include <cstdint>
#include <cstddef>

#define NBATCH 32
#define NNODE  512
#define NTIME  12
#define NCH    64
#define NM     (NTIME * NCH)            /* 768 */
#define NROWS  (NBATCH * NNODE * NTIME) /* 196608 */
#define ZELEMS ((size_t)NBATCH * NM * NNODE) /* 12582912 */

/* ------------------------------------------------------------------ */
/* Device scratch                                                      */
/* ------------------------------------------------------------------ */
__device__ float g_SW1[40 * 20];
__device__ float g_SW2[40 * 20];
__device__ float g_e1[NNODE * 20];
__device__ float g_e2[NNODE * 20];
__device__ float g_A[NNODE * NNODE];
__device__ float g_dinv[NNODE];
__device__ float g_Ls[NNODE * NNODE];
__device__ float g_T2[NNODE * NNODE];
__device__ float g_T3[NNODE * NNODE];
__device__ float g_Wid[64 * 64];

__device__ __align__(1024) __nv_bfloat16 g_ATh[3][NNODE * NNODE];
__device__ __align__(1024) __nv_bfloat16 g_ATl[3][NNODE * NNODE];
__device__ __align__(1024) __nv_bfloat16 g_Zxh[ZELEMS];
__device__ __align__(1024) __nv_bfloat16 g_Zxl[ZELEMS];
__device__ __align__(1024) __nv_bfloat16 g_Z1h[ZELEMS];
__device__ __align__(1024) __nv_bfloat16 g_Z1l[ZELEMS];
__device__ __align__(1024) __nv_bfloat16 g_Z2h[ZELEMS];
__device__ __align__(1024) __nv_bfloat16 g_Z2l[ZELEMS];
__device__ __align__(1024) __nv_bfloat16 g_Z3h[ZELEMS];
__device__ __align__(1024) __nv_bfloat16 g_Z3l[ZELEMS];

/* ------------------------------------------------------------------ */
/* PTX helpers (all plain compute_100-legal: cp.async/ldmatrix/mma)    */
/* ------------------------------------------------------------------ */
__device__ __forceinline__ uint32_t smem_to_u32(const void* p) {
    uint32_t a;
    asm("{ .reg .u64 t; cvta.to.shared.u64 t, %1; cvt.u32.u64 %0, t; }"
        : "=r"(a) : "l"(p));
    return a;
}
__device__ __forceinline__ void cpasync16(uint32_t s, const void* g) {
    asm volatile("cp.async.cg.shared.global [%0], [%1], 16;" :: "r"(s), "l"(g));
}
#define CP_COMMIT() asm volatile("cp.async.commit_group;" ::: "memory")
#define CP_WAIT1()  asm volatile("cp.async.wait_group 1;" ::: "memory")
#define CP_WAIT0()  asm volatile("cp.async.wait_group 0;" ::: "memory")

__device__ __forceinline__ void ldsm4(uint32_t& r0, uint32_t& r1,
                                      uint32_t& r2, uint32_t& r3, uint32_t a) {
    asm volatile("ldmatrix.sync.aligned.m8n8.x4.shared.b16 {%0,%1,%2,%3}, [%4];"
                 : "=r"(r0), "=r"(r1), "=r"(r2), "=r"(r3) : "r"(a));
}
__device__ __forceinline__ void mma16816(float* c, const uint32_t* a,
                                         const uint32_t* b) {
    asm volatile(
        "mma.sync.aligned.m16n8k16.row.col.f32.bf16.bf16.f32 "
        "{%0,%1,%2,%3}, {%4,%5,%6,%7}, {%8,%9}, {%0,%1,%2,%3};"
        : "+f"(c[0]), "+f"(c[1]), "+f"(c[2]), "+f"(c[3])
        : "r"(a[0]), "r"(a[1]), "r"(a[2]), "r"(a[3]), "r"(b[0]), "r"(b[1]));
}

/* ------------------------------------------------------------------ */
/* Phase A (tiny)                                                      */
/* ------------------------------------------------------------------ */
__global__ void k_softmax(const float* __restrict__ W1,
                          const float* __restrict__ W2) {
    int j = threadIdx.x;
    if (j >= 40) return;
    const float* W = (j < 20) ? W1 : W2;
    float* S = (j < 20) ? g_SW1 : g_SW2;
    int col = (j < 20) ? j : (j - 20);
    float mx = -1e30f;
    for (int k = 0; k < 40; k++) mx = fmaxf(mx, W[k * 20 + col]);
    float s = 0.f;
    for (int k = 0; k < 40; k++) s += expf(W[k * 20 + col] - mx);
    float inv = 1.f / s;
    for (int k = 0; k < 40; k++) S[k * 20 + col] = expf(W[k * 20 + col] - mx) * inv;
}

__global__ void k_embed(const float* __restrict__ emb) {
    int row = blockIdx.x;
    int lane = threadIdx.x;
    float v1 = 0.f, v2 = 0.f;
    if (lane < 20) {
        for (int k = 0; k < 40; k++) {
            float e = emb[row * 40 + k];
            v1 += e * g_SW1[k * 20 + lane];
            v2 += e * g_SW2[k * 20 + lane];
        }
    }
    float n1 = v1 * v1, n2 = v2 * v2;
    for (int off = 16; off; off >>= 1) {
        n1 += __shfl_xor_sync(0xFFFFFFFFu, n1, off);
        n2 += __shfl_xor_sync(0xFFFFFFFFu, n2, off);
    }
    if (lane < 20) {
        g_e1[row * 20 + lane] = v1 / (sqrtf(n1) + 1e-8f);
        g_e2[row * 20 + lane] = v2 / (sqrtf(n2) + 1e-8f);
    }
}

__global__ void k_buildA(const float* __restrict__ adj) {
    int v = blockIdx.x;
    __shared__ float e1v[20];
    __shared__ float red[256];
    if (threadIdx.x < 20) e1v[threadIdx.x] = g_e1[v * 20 + threadIdx.x];
    __syncthreads();
    float sum = 0.f;
    for (int w = threadIdx.x; w < NNODE; w += 256) {
        float ad = adj[v * NNODE + w];
        float val = 9e-15f;
        if (ad > 0.f) {
            float dot = 0.f;
#pragma unroll
            for (int k = 0; k < 20; k++) dot += e1v[k] * g_e2[w * 20 + k];
            val = dot + ad;
        }
        g_A[v * NNODE + w] = val;
        sum += val;
    }
    red[threadIdx.x] = sum;
    __syncthreads();
    for (int s = 128; s; s >>= 1) {
        if (threadIdx.x < s) red[threadIdx.x] += red[threadIdx.x + s];
        __syncthreads();
    }
    if (threadIdx.x == 0) g_dinv[v] = 1.0f / sqrtf(red[0]);
}

__global__ void k_Ls() {
    int v = blockIdx.x;
    float dv = g_dinv[v];
    for (int w = threadIdx.x; w < NNODE; w += 256)
        g_Ls[v * NNODE + w] = -dv * g_A[v * NNODE + w] * g_dinv[w];
}

/* C = 2*A@B - (D ? D : I), 512x512 fp32 */
__global__ void k_gemm512(const float* __restrict__ A,
                          const float* __restrict__ B,
                          const float* __restrict__ D,
                          float* __restrict__ C) {
    __shared__ float As[16][68];
    __shared__ float Bs[16][68];
    const int tx = threadIdx.x, ty = threadIdx.y;
    const int t = ty * 16 + tx;
    const int i0 = blockIdx.y * 64, j0 = blockIdx.x * 64;
    float acc[4][4] = {};
    for (int k0 = 0; k0 < NNODE; k0 += 16) {
#pragma unroll
        for (int r = 0; r < 4; r++) {
            int idx = t + r * 256;
            int ia = idx >> 4, ka = idx & 15;
            As[ka][ia] = A[(size_t)(i0 + ia) * NNODE + k0 + ka];
            int kb = idx >> 6, jb = idx & 63;
            Bs[kb][jb] = B[(size_t)(k0 + kb) * NNODE + j0 + jb];
        }
        __syncthreads();
#pragma unroll
        for (int k = 0; k < 16; k++) {
            float av[4], bv[4];
#pragma unroll
            for (int i = 0; i < 4; i++) av[i] = As[k][ty * 4 + i];
#pragma unroll
            for (int j = 0; j < 4; j++) bv[j] = Bs[k][tx * 4 + j];
#pragma unroll
            for (int i = 0; i < 4; i++)
#pragma unroll
                for (int j = 0; j < 4; j++) acc[i][j] = fmaf(av[i], bv[j], acc[i][j]);
        }
        __syncthreads();
    }
#pragma unroll
    for (int i = 0; i < 4; i++)
#pragma unroll
        for (int j = 0; j < 4; j++) {
            int gi = i0 + ty * 4 + i, gj = j0 + tx * 4 + j;
            float sub = D ? D[(size_t)gi * NNODE + gj] : (gi == gj ? 1.f : 0.f);
            C[(size_t)gi * NNODE + gj] = 2.f * acc[i][j] - sub;
        }
}

__global__ void k_wid(const float* __restrict__ mlpw) {
    int i = blockIdx.x * 256 + threadIdx.x;
    int o = i >> 6, c = i & 63;
    g_Wid[i] = mlpw[o * 832 + c] + mlpw[o * 832 + 64 + c] +
               mlpw[o * 832 + 128 + c] + mlpw[o * 832 + 192 + c];
}

/* AT[w][v] = S[v][w], split to bf16 hi/lo */
__global__ void k_att(const float* __restrict__ S,
                      __nv_bfloat16* __restrict__ Th,
                      __nv_bfloat16* __restrict__ Tl) {
    __shared__ float tile[32][33];
    int w0 = blockIdx.x * 32, v0 = blockIdx.y * 32;
    int tx = threadIdx.x, ty = threadIdx.y;
#pragma unroll
    for (int i = 0; i < 4; i++)
        tile[ty + i * 8][tx] = S[(size_t)(v0 + ty + i * 8) * NNODE + w0 + tx];
    __syncthreads();
#pragma unroll
    for (int i = 0; i < 4; i++) {
        float val = tile[tx][ty + i * 8];
        size_t idx = (size_t)(w0 + ty + i * 8) * NNODE + v0 + tx;
        __nv_bfloat16 hi = __float2bfloat16(val);
        Th[idx] = hi;
        Tl[idx] = __float2bfloat16(val - __bfloat162float(hi));
    }
}

/* Zx[b][m][v] = x[b][v][m], split hi/lo */
__global__ void k_xpose(const float* __restrict__ x,
                        __nv_bfloat16* __restrict__ Zh,
                        __nv_bfloat16* __restrict__ Zl) {
    __shared__ float tile[32][33];
    int m0 = blockIdx.x * 32, v0 = blockIdx.y * 32, b = blockIdx.z;
    int tx = threadIdx.x, ty = threadIdx.y;
#pragma unroll
    for (int i = 0; i < 4; i++)
        tile[ty + i * 8][tx] = x[((size_t)b * NNODE + v0 + ty + i * 8) * NM + m0 + tx];
    __syncthreads();
#pragma unroll
    for (int i = 0; i < 4; i++) {
        float val = tile[tx][ty + i * 8];
        size_t idx = ((size_t)b * NM + m0 + ty + i * 8) * NNODE + v0 + tx;
        __nv_bfloat16 hi = __float2bfloat16(val);
        Zh[idx] = hi;
        Zl[idx] = __float2bfloat16(val - __bfloat162float(hi));
    }
}

/* ------------------------------------------------------------------ */
/* HMMA node GEMM: Zout[b][m][w] = sum_v Zin[b][m][v] * AT[w][v]       */
/* split-3 bf16: acc = Zh*ATh + Zh*ATl + Zl*ATh (fp32 accumulate)      */
/* Block 128x128, 8 warps (2m x 4n) of 64x32, BK=16, 2-stage cp.async  */
/* ------------------------------------------------------------------ */
#define BKQ 16
#define ROWB 48                       /* (16+8) bf16 = 48 B padded row  */
#define MAT_BYTES (128 * ROWB)        /* 6144 */
#define STAGE_BYTES (4 * MAT_BYTES)   /* 24576 */
#define GEMM_SMEM (2 * STAGE_BYTES)   /* 49152 = default 48KB limit     */

__global__ void __launch_bounds__(256) k_node_gemm_mma(
    const __nv_bfloat16* __restrict__ Zh, const __nv_bfloat16* __restrict__ Zl,
    const __nv_bfloat16* __restrict__ ATh, const __nv_bfloat16* __restrict__ ATl,
    __nv_bfloat16* __restrict__ Oh, __nv_bfloat16* __restrict__ Ol) {
    extern __shared__ __align__(128) char smem[];
    const uint32_t sb = smem_to_u32(smem);
    const int tid = threadIdx.x, wid = tid >> 5, lane = tid & 31;
    const int m0 = blockIdx.x * 128;
    const int w0 = blockIdx.y * 128;
    const int b = blockIdx.z;
    const size_t zbase = ((size_t)b * NM + m0) * NNODE;
    const int warp_m = wid & 1;   /* 0..1 -> 64-row half  */
    const int warp_n = wid >> 1;  /* 0..3 -> 32-col strip */

    float acc[4][4][4];
#pragma unroll
    for (int i = 0; i < 4; i++)
#pragma unroll
        for (int j = 0; j < 4; j++)
#pragma unroll
            for (int k = 0; k < 4; k++) acc[i][j][k] = 0.f;

    /* stage loader: k-chunk it (16 wide) into stage s                  */
    auto load_stage = [&](int it, int s) {
        const int k0 = it * BKQ;
        const uint32_t sbase = sb + s * STAGE_BYTES;
#pragma unroll
        for (int i = 0; i < 4; i++) {
            int c = tid + i * 256;           /* 0..1023 */
            int mat = c >> 8;                /* 0:Zh 1:Zl 2:ATh 3:ATl  */
            int row = (c >> 1) & 127;
            int h = c & 1;                   /* 16B half of the 32B row */
            uint32_t dst = sbase + mat * MAT_BYTES + row * ROWB + h * 16;
            const __nv_bfloat16* src;
            if (mat == 0)      src = Zh + zbase + (size_t)row * NNODE + k0 + h * 8;
            else if (mat == 1) src = Zl + zbase + (size_t)row * NNODE + k0 + h * 8;
            else if (mat == 2) src = ATh + (size_t)(w0 + row) * NNODE + k0 + h * 8;
            else               src = ATl + (size_t)(w0 + row) * NNODE + k0 + h * 8;
            cpasync16(dst, src);
        }
    };

    load_stage(0, 0);
    CP_COMMIT();

    const uint32_t lrow = lane & 15;
    const uint32_t lhalf = (uint32_t)(lane >> 4) * 16;

    for (int it = 0; it < NNODE / BKQ; it++) {
        const int buf = it & 1;
        if (it < NNODE / BKQ - 1) {
            load_stage(it + 1, buf ^ 1);
            CP_COMMIT();
            CP_WAIT1();
        } else {
            CP_WAIT0();
        }
        __syncthreads();

        const uint32_t sbase = sb + buf * STAGE_BYTES;
        uint32_t ah[4][4], al[4][4], bh[4][2], bl[4][2];
#pragma unroll
        for (int mt = 0; mt < 4; mt++) {
            uint32_t a = sbase + (warp_m * 64 + mt * 16 + lrow) * ROWB + lhalf;
            ldsm4(ah[mt][0], ah[mt][1], ah[mt][2], ah[mt][3], a);
            ldsm4(al[mt][0], al[mt][1], al[mt][2], al[mt][3], a + MAT_BYTES);
        }
#pragma unroll
        for (int nh = 0; nh < 2; nh++) {
            uint32_t a = sbase + 2 * MAT_BYTES +
                         (warp_n * 32 + nh * 16 + lrow) * ROWB + lhalf;
            uint32_t r0, r1, r2, r3;
            ldsm4(r0, r1, r2, r3, a);
            bh[nh * 2][0] = r0; bh[nh * 2][1] = r2;
            bh[nh * 2 + 1][0] = r1; bh[nh * 2 + 1][1] = r3;
            ldsm4(r0, r1, r2, r3, a + MAT_BYTES);
            bl[nh * 2][0] = r0; bl[nh * 2][1] = r2;
            bl[nh * 2 + 1][0] = r1; bl[nh * 2 + 1][1] = r3;
        }
#pragma unroll
        for (int mt = 0; mt < 4; mt++)
#pragma unroll
            for (int nt = 0; nt < 4; nt++) {
                mma16816(acc[mt][nt], ah[mt], bh[nt]);
                mma16816(acc[mt][nt], ah[mt], bl[nt]);
                mma16816(acc[mt][nt], al[mt], bh[nt]);
            }
        __syncthreads();
    }

    /* epilogue: write bf16 hi/lo straight from fragments                */
    const int qr = lane >> 2;          /* fragment row 0..7   */
    const int qc = (lane & 3) * 2;     /* fragment col 0,2,4,6 */
#pragma unroll
    for (int mt = 0; mt < 4; mt++) {
#pragma unroll
        for (int nt = 0; nt < 4; nt++) {
            const int row0 = m0 + warp_m * 64 + mt * 16 + qr;
            const int col = w0 + warp_n * 32 + nt * 8 + qc;
            const float* c = acc[mt][nt];
            size_t i0 = ((size_t)b * NM + row0) * NNODE + col;
            size_t i1 = i0 + (size_t)8 * NNODE;
            __nv_bfloat16 h0 = __float2bfloat16(c[0]);
            __nv_bfloat16 h1 = __float2bfloat16(c[1]);
            __nv_bfloat16 h2 = __float2bfloat16(c[2]);
            __nv_bfloat16 h3 = __float2bfloat16(c[3]);
            __nv_bfloat162 hp, lp;
            hp.x = h0; hp.y = h1;
            lp.x = __float2bfloat16(c[0] - __bfloat162float(h0));
            lp.y = __float2bfloat16(c[1] - __bfloat162float(h1));
            *(__nv_bfloat162*)(Oh + i0) = hp;
            *(__nv_bfloat162*)(Ol + i0) = lp;
            hp.x = h2; hp.y = h3;
            lp.x = __float2bfloat16(c[2] - __bfloat162float(h2));
            lp.y = __float2bfloat16(c[3] - __bfloat162float(h3));
            *(__nv_bfloat162*)(Oh + i1) = hp;
            *(__nv_bfloat162*)(Ol + i1) = lp;
        }
    }
}

/* ------------------------------------------------------------------ */
/* Identity channel mix (orig layout)                                  */
/* ------------------------------------------------------------------ */
__global__ void __launch_bounds__(256) k_chanmix(
    const float* __restrict__ Yv, const float* __restrict__ W, int wstride,
    float* __restrict__ out) {
    __shared__ float Ws[64][64];
    __shared__ float Ys[64][68];
    const int t = threadIdx.x;
    const size_t r0 = (size_t)blockIdx.x * 64;
    for (int i = t; i < 4096; i += 256) {
        int o = i >> 6, c = i & 63;
        Ws[c][o] = W[(size_t)o * wstride + c];
    }
    for (int i = t; i < 1024; i += 256) {
        int row = i >> 4, c4 = (i & 15) * 4;
        float4 v = *(const float4*)(Yv + (r0 + row) * 64 + c4);
        Ys[row][c4 + 0] = v.x;
        Ys[row][c4 + 1] = v.y;
        Ys[row][c4 + 2] = v.z;
        Ys[row][c4 + 3] = v.w;
    }
    __syncthreads();
    const int tx = t & 15, ty = t >> 4;
    float acc[4][4] = {};
#pragma unroll
    for (int c = 0; c < 64; c++) {
        float yv[4], wv[4];
#pragma unroll
        for (int i = 0; i < 4; i++) yv[i] = Ys[ty * 4 + i][c];
#pragma unroll
        for (int j = 0; j < 4; j++) wv[j] = Ws[c][tx * 4 + j];
#pragma unroll
        for (int i = 0; i < 4; i++)
#pragma unroll
            for (int j = 0; j < 4; j++) acc[i][j] = fmaf(yv[i], wv[j], acc[i][j]);
    }
#pragma unroll
    for (int i = 0; i < 4; i++) {
        float* po = out + (r0 + ty * 4 + i) * 64 + tx * 4;
        *(float4*)po = make_float4(acc[i][0], acc[i][1], acc[i][2], acc[i][3]);
    }
}

/* ------------------------------------------------------------------ */
/* Chain channel mix (Z domain, 3 hops) + optional bias/residual/relu  */
/* ------------------------------------------------------------------ */
__global__ void __launch_bounds__(256) k_chanmix_chain(
    const __nv_bfloat16* __restrict__ Z1h, const __nv_bfloat16* __restrict__ Z1l,
    const __nv_bfloat16* __restrict__ Z2h, const __nv_bfloat16* __restrict__ Z2l,
    const __nv_bfloat16* __restrict__ Z3h, const __nv_bfloat16* __restrict__ Z3l,
    const float* __restrict__ mlpw, int j0,
    float* __restrict__ out,
    const float* __restrict__ x, const float* __restrict__ bias, int do_final) {
    __shared__ float Ws[64][65];
    __shared__ float Ys[64][65];
    const int wblk = blockIdx.x; /* 0..7 */
    const int t = blockIdx.y;    /* 0..11 */
    const int b = blockIdx.z;
    const int tid = threadIdx.x, tx = tid & 15, ty = tid >> 4;
    const __nv_bfloat16* Zh[3] = {Z1h, Z2h, Z3h};
    const __nv_bfloat16* Zl[3] = {Z1l, Z2l, Z3l};
    float acc[4][4] = {};
#pragma unroll 1
    for (int h = 0; h < 3; h++) {
        for (int i = tid; i < 4096; i += 256) {
            int o = i >> 6, c = i & 63;
            Ws[c][o] = mlpw[(size_t)o * 832 + (j0 + h) * 64 + c];
        }
        for (int i = tid; i < 2048; i += 256) {
            int c = i >> 5, p = i & 31;
            size_t idx = ((size_t)b * NM + t * 64 + c) * NNODE + wblk * 64 + p * 2;
            __nv_bfloat162 vh = *(const __nv_bfloat162*)(Zh[h] + idx);
            __nv_bfloat162 vl = *(const __nv_bfloat162*)(Zl[h] + idx);
            Ys[c][p * 2]     = __bfloat162float(vh.x) + __bfloat162float(vl.x);
            Ys[c][p * 2 + 1] = __bfloat162float(vh.y) + __bfloat162float(vl.y);
        }
        __syncthreads();
#pragma unroll
        for (int c = 0; c < 64; c++) {
            float yv[4], wv[4];
#pragma unroll
            for (int i = 0; i < 4; i++) yv[i] = Ys[c][ty * 4 + i];
#pragma unroll
            for (int j = 0; j < 4; j++) wv[j] = Ws[c][tx * 4 + j];
#pragma unroll
            for (int i = 0; i < 4; i++)
#pragma unroll
                for (int j = 0; j < 4; j++) acc[i][j] = fmaf(yv[i], wv[j], acc[i][j]);
        }
        __syncthreads();
    }
#pragma unroll
    for (int i = 0; i < 4; i++) {
        size_t r = ((size_t)(b * NNODE + wblk * 64 + ty * 4 + i) * NTIME + t);
        float* po = out + r * 64 + tx * 4;
        float4 v = *(float4*)po;
        v.x += acc[i][0];
        v.y += acc[i][1];
        v.z += acc[i][2];
        v.w += acc[i][3];
        if (do_final) {
            const float4 bb = *(const float4*)(bias + tx * 4);
            const float4 xo = *(const float4*)(x + r * 64 + tx * 4);
            v.x = fmaxf(v.x + bb.x + xo.x, 0.f);
            v.y = fmaxf(v.y + bb.y + xo.y, 0.f);
            v.z = fmaxf(v.z + bb.z + xo.z, 0.f);
            v.w = fmaxf(v.w + bb.w + xo.w, 0.f);
        }
        *(float4*)po = v;
    }
}

/* ------------------------------------------------------------------ */
extern "C" void kernel_launch(void* const* d_in, const int* in_sizes, int n_in,
                              void* d_out, int out_size) {
    (void)in_sizes; (void)n_in; (void)out_size;
    const float* x    = (const float*)d_in[0];
    const float* adj  = (const float*)d_in[1];
    const float* emb  = (const float*)d_in[2];
    const float* W1   = (const float*)d_in[3];
    const float* W2   = (const float*)d_in[4];
    const float* mlpw = (const float*)d_in[5];
    const float* mlpb = (const float*)d_in[6];
    float* out = (float*)d_out;

    float *pLs, *pT2, *pT3, *pWid;
    __nv_bfloat16 *pATh, *pATl, *pZxh, *pZxl;
    __nv_bfloat16 *pZ1h, *pZ1l, *pZ2h, *pZ2l, *pZ3h, *pZ3l;
    cudaGetSymbolAddress((void**)&pLs, g_Ls);
    cudaGetSymbolAddress((void**)&pT2, g_T2);
    cudaGetSymbolAddress((void**)&pT3, g_T3);
    cudaGetSymbolAddress((void**)&pWid, g_Wid);
    cudaGetSymbolAddress((void**)&pATh, g_ATh);
    cudaGetSymbolAddress((void**)&pATl, g_ATl);
    cudaGetSymbolAddress((void**)&pZxh, g_Zxh);
    cudaGetSymbolAddress((void**)&pZxl, g_Zxl);
    cudaGetSymbolAddress((void**)&pZ1h, g_Z1h);
    cudaGetSymbolAddress((void**)&pZ1l, g_Z1l);
    cudaGetSymbolAddress((void**)&pZ2h, g_Z2h);
    cudaGetSymbolAddress((void**)&pZ2l, g_Z2l);
    cudaGetSymbolAddress((void**)&pZ3h, g_Z3h);
    cudaGetSymbolAddress((void**)&pZ3l, g_Z3l);

    /* Phase A */
    k_softmax<<<1, 64>>>(W1, W2);
    k_embed<<<512, 32>>>(emb);
    k_buildA<<<512, 256>>>(adj);
    k_Ls<<<512, 256>>>();
    dim3 g512(8, 8), b512(16, 16);
    k_gemm512<<<g512, b512>>>(pLs, pLs, (const float*)nullptr, pT2);
    k_gemm512<<<g512, b512>>>(pLs, pT2, pLs, pT3);
    dim3 gat(16, 16), bat(32, 8);
    k_att<<<gat, bat>>>(pLs, pATh + 0 * (size_t)NNODE * NNODE, pATl + 0 * (size_t)NNODE * NNODE);
    k_att<<<gat, bat>>>(pT2, pATh + 1 * (size_t)NNODE * NNODE, pATl + 1 * (size_t)NNODE * NNODE);
    k_att<<<gat, bat>>>(pT3, pATh + 2 * (size_t)NNODE * NNODE, pATl + 2 * (size_t)NNODE * NNODE);
    k_wid<<<16, 256>>>(mlpw);

    /* identity blocks -> out (non-accumulating write) */
    k_chanmix<<<NROWS / 64, 256>>>(x, pWid, 64, out);

    /* transpose+split x -> Zx */
    dim3 gx(24, 16, 32), bx(32, 8);
    k_xpose<<<gx, bx>>>(x, pZxh, pZxl);

    /* 3 chains of 3 hops each on HMMA tensor cores */
    dim3 gg(6, 4, 32);
    dim3 gc(8, 12, 32);
    for (int s = 0; s < 3; s++) {
        const __nv_bfloat16* ah = pATh + (size_t)s * NNODE * NNODE;
        const __nv_bfloat16* al = pATl + (size_t)s * NNODE * NNODE;
        k_node_gemm_mma<<<gg, 256, GEMM_SMEM>>>(pZxh, pZxl, ah, al, pZ1h, pZ1l);
        k_node_gemm_mma<<<gg, 256, GEMM_SMEM>>>(pZ1h, pZ1l, ah, al, pZ2h, pZ2l);
        k_node_gemm_mma<<<gg, 256, GEMM_SMEM>>>(pZ2h, pZ2l, ah, al, pZ3h, pZ3l);
        k_chanmix_chain<<<gc, 256>>>(pZ1h, pZ1l, pZ2h, pZ2l, pZ3h, pZ3l,
                                     mlpw, 4 + 3 * s, out, x, mlpb, s == 2 ? 1 : 0);
    }
}

// round 7
// speedup vs baseline: 1.6386x; 1.0156x over previous
#include <cuda_runtime.h>
#include <cuda_bf16.h>
#include <cstdint>
#include <cstddef>

#define NBATCH 32
#define NNODE  512
#define NTIME  12
#define NCH    64
#define NM     (NTIME * NCH)            /* 768 */
#define NROWS  (NBATCH * NNODE * NTIME) /* 196608 */
#define ZELEMS ((size_t)NBATCH * NM * NNODE) /* 12582912 */

/* ------------------------------------------------------------------ */
/* Device scratch                                                      */
/* ------------------------------------------------------------------ */
__device__ float g_SW1[40 * 20];
__device__ float g_SW2[40 * 20];
__device__ float g_e1[NNODE * 20];
__device__ float g_e2[NNODE * 20];
__device__ float g_A[NNODE * NNODE];
__device__ float g_dinv[NNODE];
__device__ float g_Ls[NNODE * NNODE];
__device__ float g_T2[NNODE * NNODE];
__device__ float g_T3[NNODE * NNODE];
__device__ float g_Wid[64 * 64];

__device__ __align__(1024) __nv_bfloat16 g_ATh[3][NNODE * NNODE];
__device__ __align__(1024) __nv_bfloat16 g_ATl[3][NNODE * NNODE];
__device__ __align__(1024) __nv_bfloat16 g_Zxh[ZELEMS];
__device__ __align__(1024) __nv_bfloat16 g_Zxl[ZELEMS];
__device__ __align__(1024) __nv_bfloat16 g_Z1h[ZELEMS];
__device__ __align__(1024) __nv_bfloat16 g_Z1l[ZELEMS];
__device__ __align__(1024) __nv_bfloat16 g_Z2h[ZELEMS];
__device__ __align__(1024) __nv_bfloat16 g_Z2l[ZELEMS];
__device__ __align__(1024) __nv_bfloat16 g_Z3h[ZELEMS];
__device__ __align__(1024) __nv_bfloat16 g_Z3l[ZELEMS];

/* ------------------------------------------------------------------ */
/* PTX helpers (all plain compute_100-legal: cp.async/ldmatrix/mma)    */
/* ------------------------------------------------------------------ */
__device__ __forceinline__ uint32_t smem_to_u32(const void* p) {
    uint32_t a;
    asm("{ .reg .u64 t; cvta.to.shared.u64 t, %1; cvt.u32.u64 %0, t; }"
        : "=r"(a) : "l"(p));
    return a;
}
__device__ __forceinline__ void cpasync16(uint32_t s, const void* g) {
    asm volatile("cp.async.cg.shared.global [%0], [%1], 16;" :: "r"(s), "l"(g));
}
#define CP_COMMIT() asm volatile("cp.async.commit_group;" ::: "memory")
#define CP_WAIT1()  asm volatile("cp.async.wait_group 1;" ::: "memory")
#define CP_WAIT0()  asm volatile("cp.async.wait_group 0;" ::: "memory")

__device__ __forceinline__ void ldsm4(uint32_t& r0, uint32_t& r1,
                                      uint32_t& r2, uint32_t& r3, uint32_t a) {
    asm volatile("ldmatrix.sync.aligned.m8n8.x4.shared.b16 {%0,%1,%2,%3}, [%4];"
                 : "=r"(r0), "=r"(r1), "=r"(r2), "=r"(r3) : "r"(a));
}
__device__ __forceinline__ void mma16816(float* c, const uint32_t* a,
                                         const uint32_t* b) {
    asm volatile(
        "mma.sync.aligned.m16n8k16.row.col.f32.bf16.bf16.f32 "
        "{%0,%1,%2,%3}, {%4,%5,%6,%7}, {%8,%9}, {%0,%1,%2,%3};"
        : "+f"(c[0]), "+f"(c[1]), "+f"(c[2]), "+f"(c[3])
        : "r"(a[0]), "r"(a[1]), "r"(a[2]), "r"(a[3]), "r"(b[0]), "r"(b[1]));
}

/* ------------------------------------------------------------------ */
/* Phase A (tiny)                                                      */
/* ------------------------------------------------------------------ */
__global__ void k_softmax(const float* __restrict__ W1,
                          const float* __restrict__ W2) {
    int j = threadIdx.x;
    if (j >= 40) return;
    const float* W = (j < 20) ? W1 : W2;
    float* S = (j < 20) ? g_SW1 : g_SW2;
    int col = (j < 20) ? j : (j - 20);
    float mx = -1e30f;
    for (int k = 0; k < 40; k++) mx = fmaxf(mx, W[k * 20 + col]);
    float s = 0.f;
    for (int k = 0; k < 40; k++) s += expf(W[k * 20 + col] - mx);
    float inv = 1.f / s;
    for (int k = 0; k < 40; k++) S[k * 20 + col] = expf(W[k * 20 + col] - mx) * inv;
}

__global__ void k_embed(const float* __restrict__ emb) {
    int row = blockIdx.x;
    int lane = threadIdx.x;
    float v1 = 0.f, v2 = 0.f;
    if (lane < 20) {
        for (int k = 0; k < 40; k++) {
            float e = emb[row * 40 + k];
            v1 += e * g_SW1[k * 20 + lane];
            v2 += e * g_SW2[k * 20 + lane];
        }
    }
    float n1 = v1 * v1, n2 = v2 * v2;
    for (int off = 16; off; off >>= 1) {
        n1 += __shfl_xor_sync(0xFFFFFFFFu, n1, off);
        n2 += __shfl_xor_sync(0xFFFFFFFFu, n2, off);
    }
    if (lane < 20) {
        g_e1[row * 20 + lane] = v1 / (sqrtf(n1) + 1e-8f);
        g_e2[row * 20 + lane] = v2 / (sqrtf(n2) + 1e-8f);
    }
}

__global__ void k_buildA(const float* __restrict__ adj) {
    int v = blockIdx.x;
    __shared__ float e1v[20];
    __shared__ float red[256];
    if (threadIdx.x < 20) e1v[threadIdx.x] = g_e1[v * 20 + threadIdx.x];
    __syncthreads();
    float sum = 0.f;
    for (int w = threadIdx.x; w < NNODE; w += 256) {
        float ad = adj[v * NNODE + w];
        float val = 9e-15f;
        if (ad > 0.f) {
            float dot = 0.f;
#pragma unroll
            for (int k = 0; k < 20; k++) dot += e1v[k] * g_e2[w * 20 + k];
            val = dot + ad;
        }
        g_A[v * NNODE + w] = val;
        sum += val;
    }
    red[threadIdx.x] = sum;
    __syncthreads();
    for (int s = 128; s; s >>= 1) {
        if (threadIdx.x < s) red[threadIdx.x] += red[threadIdx.x + s];
        __syncthreads();
    }
    if (threadIdx.x == 0) g_dinv[v] = 1.0f / sqrtf(red[0]);
}

__global__ void k_Ls() {
    int v = blockIdx.x;
    float dv = g_dinv[v];
    for (int w = threadIdx.x; w < NNODE; w += 256)
        g_Ls[v * NNODE + w] = -dv * g_A[v * NNODE + w] * g_dinv[w];
}

/* C = 2*A@B - (D ? D : I), 512x512 fp32 */
__global__ void k_gemm512(const float* __restrict__ A,
                          const float* __restrict__ B,
                          const float* __restrict__ D,
                          float* __restrict__ C) {
    __shared__ float As[16][68];
    __shared__ float Bs[16][68];
    const int tx = threadIdx.x, ty = threadIdx.y;
    const int t = ty * 16 + tx;
    const int i0 = blockIdx.y * 64, j0 = blockIdx.x * 64;
    float acc[4][4] = {};
    for (int k0 = 0; k0 < NNODE; k0 += 16) {
#pragma unroll
        for (int r = 0; r < 4; r++) {
            int idx = t + r * 256;
            int ia = idx >> 4, ka = idx & 15;
            As[ka][ia] = A[(size_t)(i0 + ia) * NNODE + k0 + ka];
            int kb = idx >> 6, jb = idx & 63;
            Bs[kb][jb] = B[(size_t)(k0 + kb) * NNODE + j0 + jb];
        }
        __syncthreads();
#pragma unroll
        for (int k = 0; k < 16; k++) {
            float av[4], bv[4];
#pragma unroll
            for (int i = 0; i < 4; i++) av[i] = As[k][ty * 4 + i];
#pragma unroll
            for (int j = 0; j < 4; j++) bv[j] = Bs[k][tx * 4 + j];
#pragma unroll
            for (int i = 0; i < 4; i++)
#pragma unroll
                for (int j = 0; j < 4; j++) acc[i][j] = fmaf(av[i], bv[j], acc[i][j]);
        }
        __syncthreads();
    }
#pragma unroll
    for (int i = 0; i < 4; i++)
#pragma unroll
        for (int j = 0; j < 4; j++) {
            int gi = i0 + ty * 4 + i, gj = j0 + tx * 4 + j;
            float sub = D ? D[(size_t)gi * NNODE + gj] : (gi == gj ? 1.f : 0.f);
            C[(size_t)gi * NNODE + gj] = 2.f * acc[i][j] - sub;
        }
}

__global__ void k_wid(const float* __restrict__ mlpw) {
    int i = blockIdx.x * 256 + threadIdx.x;
    int o = i >> 6, c = i & 63;
    g_Wid[i] = mlpw[o * 832 + c] + mlpw[o * 832 + 64 + c] +
               mlpw[o * 832 + 128 + c] + mlpw[o * 832 + 192 + c];
}

/* AT[w][v] = S[v][w], split to bf16 hi/lo */
__global__ void k_att(const float* __restrict__ S,
                      __nv_bfloat16* __restrict__ Th,
                      __nv_bfloat16* __restrict__ Tl) {
    __shared__ float tile[32][33];
    int w0 = blockIdx.x * 32, v0 = blockIdx.y * 32;
    int tx = threadIdx.x, ty = threadIdx.y;
#pragma unroll
    for (int i = 0; i < 4; i++)
        tile[ty + i * 8][tx] = S[(size_t)(v0 + ty + i * 8) * NNODE + w0 + tx];
    __syncthreads();
#pragma unroll
    for (int i = 0; i < 4; i++) {
        float val = tile[tx][ty + i * 8];
        size_t idx = (size_t)(w0 + ty + i * 8) * NNODE + v0 + tx;
        __nv_bfloat16 hi = __float2bfloat16(val);
        Th[idx] = hi;
        Tl[idx] = __float2bfloat16(val - __bfloat162float(hi));
    }
}

/* Zx[b][m][v] = x[b][v][m], split hi/lo */
__global__ void k_xpose(const float* __restrict__ x,
                        __nv_bfloat16* __restrict__ Zh,
                        __nv_bfloat16* __restrict__ Zl) {
    __shared__ float tile[32][33];
    int m0 = blockIdx.x * 32, v0 = blockIdx.y * 32, b = blockIdx.z;
    int tx = threadIdx.x, ty = threadIdx.y;
#pragma unroll
    for (int i = 0; i < 4; i++)
        tile[ty + i * 8][tx] = x[((size_t)b * NNODE + v0 + ty + i * 8) * NM + m0 + tx];
    __syncthreads();
#pragma unroll
    for (int i = 0; i < 4; i++) {
        float val = tile[tx][ty + i * 8];
        size_t idx = ((size_t)b * NM + m0 + ty + i * 8) * NNODE + v0 + tx;
        __nv_bfloat16 hi = __float2bfloat16(val);
        Zh[idx] = hi;
        Zl[idx] = __float2bfloat16(val - __bfloat162float(hi));
    }
}

/* ------------------------------------------------------------------ */
/* HMMA node GEMM: Zout[b][m][w] = sum_v Zin[b][m][v] * AT[w][v]       */
/* split-3 bf16: acc = Zh*ATh + Zh*ATl + Zl*ATh (fp32 accumulate)      */
/* Block 128x128, 8 warps (2m x 4n) of 64x32, BK=16                    */
/* 3-stage cp.async ring, ONE __syncthreads per iteration              */
/* ------------------------------------------------------------------ */
#define BKQ 16
#define ROWB 48                       /* (16+8) bf16 = 48 B padded row  */
#define MAT_BYTES (128 * ROWB)        /* 6144 */
#define STAGE_BYTES (4 * MAT_BYTES)   /* 24576 */
#define NSTAGE 3
#define GEMM_SMEM (NSTAGE * STAGE_BYTES) /* 73728 -> opt-in attribute   */

__global__ void __launch_bounds__(256) k_node_gemm_mma(
    const __nv_bfloat16* __restrict__ Zh, const __nv_bfloat16* __restrict__ Zl,
    const __nv_bfloat16* __restrict__ ATh, const __nv_bfloat16* __restrict__ ATl,
    __nv_bfloat16* __restrict__ Oh, __nv_bfloat16* __restrict__ Ol) {
    extern __shared__ __align__(128) char smem[];
    const uint32_t sb = smem_to_u32(smem);
    const int tid = threadIdx.x, wid = tid >> 5, lane = tid & 31;
    const int m0 = blockIdx.x * 128;
    const int w0 = blockIdx.y * 128;
    const int b = blockIdx.z;
    const size_t zbase = ((size_t)b * NM + m0) * NNODE;
    const int warp_m = wid & 1;   /* 0..1 -> 64-row half  */
    const int warp_n = wid >> 1;  /* 0..3 -> 32-col strip */

    float acc[4][4][4];
#pragma unroll
    for (int i = 0; i < 4; i++)
#pragma unroll
        for (int j = 0; j < 4; j++)
#pragma unroll
            for (int k = 0; k < 4; k++) acc[i][j][k] = 0.f;

    /* stage loader: k-chunk it (16 wide) into stage s                  */
    auto load_stage = [&](int it, int s) {
        const int k0 = it * BKQ;
        const uint32_t sbase = sb + s * STAGE_BYTES;
#pragma unroll
        for (int i = 0; i < 4; i++) {
            int c = tid + i * 256;           /* 0..1023 */
            int mat = c >> 8;                /* 0:Zh 1:Zl 2:ATh 3:ATl  */
            int row = (c >> 1) & 127;
            int h = c & 1;                   /* 16B half of the 32B row */
            uint32_t dst = sbase + mat * MAT_BYTES + row * ROWB + h * 16;
            const __nv_bfloat16* src;
            if (mat == 0)      src = Zh + zbase + (size_t)row * NNODE + k0 + h * 8;
            else if (mat == 1) src = Zl + zbase + (size_t)row * NNODE + k0 + h * 8;
            else if (mat == 2) src = ATh + (size_t)(w0 + row) * NNODE + k0 + h * 8;
            else               src = ATl + (size_t)(w0 + row) * NNODE + k0 + h * 8;
            cpasync16(dst, src);
        }
    };

    load_stage(0, 0);
    CP_COMMIT();
    load_stage(1, 1);
    CP_COMMIT();

    const uint32_t lrow = lane & 15;
    const uint32_t lhalf = (uint32_t)(lane >> 4) * 16;
    const int NIT = NNODE / BKQ; /* 32 */

    for (int it = 0; it < NIT; it++) {
        /* make chunk `it` resident (pending after this: at most chunk it+1) */
        if (it < NIT - 1) CP_WAIT1(); else CP_WAIT0();
        __syncthreads();
        /* prefetch chunk it+2 into ring slot (it+2)%3 == (it-1)%3 (already
           fully consumed by every warp before the barrier above)            */
        if (it + 2 < NIT) {
            load_stage(it + 2, (it + 2) % NSTAGE);
            CP_COMMIT();
        }

        const uint32_t sbase = sb + (it % NSTAGE) * STAGE_BYTES;
        uint32_t ah[4][4], al[4][4], bh[4][2], bl[4][2];
#pragma unroll
        for (int mt = 0; mt < 4; mt++) {
            uint32_t a = sbase + (warp_m * 64 + mt * 16 + lrow) * ROWB + lhalf;
            ldsm4(ah[mt][0], ah[mt][1], ah[mt][2], ah[mt][3], a);
            ldsm4(al[mt][0], al[mt][1], al[mt][2], al[mt][3], a + MAT_BYTES);
        }
#pragma unroll
        for (int nh = 0; nh < 2; nh++) {
            uint32_t a = sbase + 2 * MAT_BYTES +
                         (warp_n * 32 + nh * 16 + lrow) * ROWB + lhalf;
            uint32_t r0, r1, r2, r3;
            ldsm4(r0, r1, r2, r3, a);
            bh[nh * 2][0] = r0; bh[nh * 2][1] = r2;
            bh[nh * 2 + 1][0] = r1; bh[nh * 2 + 1][1] = r3;
            ldsm4(r0, r1, r2, r3, a + MAT_BYTES);
            bl[nh * 2][0] = r0; bl[nh * 2][1] = r2;
            bl[nh * 2 + 1][0] = r1; bl[nh * 2 + 1][1] = r3;
        }
#pragma unroll
        for (int mt = 0; mt < 4; mt++)
#pragma unroll
            for (int nt = 0; nt < 4; nt++) {
                mma16816(acc[mt][nt], ah[mt], bh[nt]);
                mma16816(acc[mt][nt], ah[mt], bl[nt]);
                mma16816(acc[mt][nt], al[mt], bh[nt]);
            }
    }

    /* epilogue: write bf16 hi/lo straight from fragments                */
    const int qr = lane >> 2;          /* fragment row 0..7   */
    const int qc = (lane & 3) * 2;     /* fragment col 0,2,4,6 */
#pragma unroll
    for (int mt = 0; mt < 4; mt++) {
#pragma unroll
        for (int nt = 0; nt < 4; nt++) {
            const int row0 = m0 + warp_m * 64 + mt * 16 + qr;
            const int col = w0 + warp_n * 32 + nt * 8 + qc;
            const float* c = acc[mt][nt];
            size_t i0 = ((size_t)b * NM + row0) * NNODE + col;
            size_t i1 = i0 + (size_t)8 * NNODE;
            __nv_bfloat16 h0 = __float2bfloat16(c[0]);
            __nv_bfloat16 h1 = __float2bfloat16(c[1]);
            __nv_bfloat16 h2 = __float2bfloat16(c[2]);
            __nv_bfloat16 h3 = __float2bfloat16(c[3]);
            __nv_bfloat162 hp, lp;
            hp.x = h0; hp.y = h1;
            lp.x = __float2bfloat16(c[0] - __bfloat162float(h0));
            lp.y = __float2bfloat16(c[1] - __bfloat162float(h1));
            *(__nv_bfloat162*)(Oh + i0) = hp;
            *(__nv_bfloat162*)(Ol + i0) = lp;
            hp.x = h2; hp.y = h3;
            lp.x = __float2bfloat16(c[2] - __bfloat162float(h2));
            lp.y = __float2bfloat16(c[3] - __bfloat162float(h3));
            *(__nv_bfloat162*)(Oh + i1) = hp;
            *(__nv_bfloat162*)(Ol + i1) = lp;
        }
    }
}

/* ------------------------------------------------------------------ */
/* Identity channel mix (orig layout)                                  */
/* ------------------------------------------------------------------ */
__global__ void __launch_bounds__(256) k_chanmix(
    const float* __restrict__ Yv, const float* __restrict__ W, int wstride,
    float* __restrict__ out) {
    __shared__ float Ws[64][64];
    __shared__ float Ys[64][68];
    const int t = threadIdx.x;
    const size_t r0 = (size_t)blockIdx.x * 64;
    for (int i = t; i < 4096; i += 256) {
        int o = i >> 6, c = i & 63;
        Ws[c][o] = W[(size_t)o * wstride + c];
    }
    for (int i = t; i < 1024; i += 256) {
        int row = i >> 4, c4 = (i & 15) * 4;
        float4 v = *(const float4*)(Yv + (r0 + row) * 64 + c4);
        Ys[row][c4 + 0] = v.x;
        Ys[row][c4 + 1] = v.y;
        Ys[row][c4 + 2] = v.z;
        Ys[row][c4 + 3] = v.w;
    }
    __syncthreads();
    const int tx = t & 15, ty = t >> 4;
    float acc[4][4] = {};
#pragma unroll
    for (int c = 0; c < 64; c++) {
        float yv[4], wv[4];
#pragma unroll
        for (int i = 0; i < 4; i++) yv[i] = Ys[ty * 4 + i][c];
#pragma unroll
        for (int j = 0; j < 4; j++) wv[j] = Ws[c][tx * 4 + j];
#pragma unroll
        for (int i = 0; i < 4; i++)
#pragma unroll
            for (int j = 0; j < 4; j++) acc[i][j] = fmaf(yv[i], wv[j], acc[i][j]);
    }
#pragma unroll
    for (int i = 0; i < 4; i++) {
        float* po = out + (r0 + ty * 4 + i) * 64 + tx * 4;
        *(float4*)po = make_float4(acc[i][0], acc[i][1], acc[i][2], acc[i][3]);
    }
}

/* ------------------------------------------------------------------ */
/* Chain channel mix (Z domain, 3 hops) + optional bias/residual/relu  */
/* ------------------------------------------------------------------ */
__global__ void __launch_bounds__(256) k_chanmix_chain(
    const __nv_bfloat16* __restrict__ Z1h, const __nv_bfloat16* __restrict__ Z1l,
    const __nv_bfloat16* __restrict__ Z2h, const __nv_bfloat16* __restrict__ Z2l,
    const __nv_bfloat16* __restrict__ Z3h, const __nv_bfloat16* __restrict__ Z3l,
    const float* __restrict__ mlpw, int j0,
    float* __restrict__ out,
    const float* __restrict__ x, const float* __restrict__ bias, int do_final) {
    __shared__ float Ws[64][65];
    __shared__ float Ys[64][65];
    const int wblk = blockIdx.x; /* 0..7 */
    const int t = blockIdx.y;    /* 0..11 */
    const int b = blockIdx.z;
    const int tid = threadIdx.x, tx = tid & 15, ty = tid >> 4;
    const __nv_bfloat16* Zh[3] = {Z1h, Z2h, Z3h};
    const __nv_bfloat16* Zl[3] = {Z1l, Z2l, Z3l};
    float acc[4][4] = {};
#pragma unroll 1
    for (int h = 0; h < 3; h++) {
        for (int i = tid; i < 4096; i += 256) {
            int o = i >> 6, c = i & 63;
            Ws[c][o] = mlpw[(size_t)o * 832 + (j0 + h) * 64 + c];
        }
        for (int i = tid; i < 2048; i += 256) {
            int c = i >> 5, p = i & 31;
            size_t idx = ((size_t)b * NM + t * 64 + c) * NNODE + wblk * 64 + p * 2;
            __nv_bfloat162 vh = *(const __nv_bfloat162*)(Zh[h] + idx);
            __nv_bfloat162 vl = *(const __nv_bfloat162*)(Zl[h] + idx);
            Ys[c][p * 2]     = __bfloat162float(vh.x) + __bfloat162float(vl.x);
            Ys[c][p * 2 + 1] = __bfloat162float(vh.y) + __bfloat162float(vl.y);
        }
        __syncthreads();
#pragma unroll
        for (int c = 0; c < 64; c++) {
            float yv[4], wv[4];
#pragma unroll
            for (int i = 0; i < 4; i++) yv[i] = Ys[c][ty * 4 + i];
#pragma unroll
            for (int j = 0; j < 4; j++) wv[j] = Ws[c][tx * 4 + j];
#pragma unroll
            for (int i = 0; i < 4; i++)
#pragma unroll
                for (int j = 0; j < 4; j++) acc[i][j] = fmaf(yv[i], wv[j], acc[i][j]);
        }
        __syncthreads();
    }
#pragma unroll
    for (int i = 0; i < 4; i++) {
        size_t r = ((size_t)(b * NNODE + wblk * 64 + ty * 4 + i) * NTIME + t);
        float* po = out + r * 64 + tx * 4;
        float4 v = *(float4*)po;
        v.x += acc[i][0];
        v.y += acc[i][1];
        v.z += acc[i][2];
        v.w += acc[i][3];
        if (do_final) {
            const float4 bb = *(const float4*)(bias + tx * 4);
            const float4 xo = *(const float4*)(x + r * 64 + tx * 4);
            v.x = fmaxf(v.x + bb.x + xo.x, 0.f);
            v.y = fmaxf(v.y + bb.y + xo.y, 0.f);
            v.z = fmaxf(v.z + bb.z + xo.z, 0.f);
            v.w = fmaxf(v.w + bb.w + xo.w, 0.f);
        }
        *(float4*)po = v;
    }
}

/* ------------------------------------------------------------------ */
extern "C" void kernel_launch(void* const* d_in, const int* in_sizes, int n_in,
                              void* d_out, int out_size) {
    (void)in_sizes; (void)n_in; (void)out_size;
    const float* x    = (const float*)d_in[0];
    const float* adj  = (const float*)d_in[1];
    const float* emb  = (const float*)d_in[2];
    const float* W1   = (const float*)d_in[3];
    const float* W2   = (const float*)d_in[4];
    const float* mlpw = (const float*)d_in[5];
    const float* mlpb = (const float*)d_in[6];
    float* out = (float*)d_out;

    float *pLs, *pT2, *pT3, *pWid;
    __nv_bfloat16 *pATh, *pATl, *pZxh, *pZxl;
    __nv_bfloat16 *pZ1h, *pZ1l, *pZ2h, *pZ2l, *pZ3h, *pZ3l;
    cudaGetSymbolAddress((void**)&pLs, g_Ls);
    cudaGetSymbolAddress((void**)&pT2, g_T2);
    cudaGetSymbolAddress((void**)&pT3, g_T3);
    cudaGetSymbolAddress((void**)&pWid, g_Wid);
    cudaGetSymbolAddress((void**)&pATh, g_ATh);
    cudaGetSymbolAddress((void**)&pATl, g_ATl);
    cudaGetSymbolAddress((void**)&pZxh, g_Zxh);
    cudaGetSymbolAddress((void**)&pZxl, g_Zxl);
    cudaGetSymbolAddress((void**)&pZ1h, g_Z1h);
    cudaGetSymbolAddress((void**)&pZ1l, g_Z1l);
    cudaGetSymbolAddress((void**)&pZ2h, g_Z2h);
    cudaGetSymbolAddress((void**)&pZ2l, g_Z2l);
    cudaGetSymbolAddress((void**)&pZ3h, g_Z3h);
    cudaGetSymbolAddress((void**)&pZ3l, g_Z3l);

    cudaFuncSetAttribute(k_node_gemm_mma,
                         cudaFuncAttributeMaxDynamicSharedMemorySize, GEMM_SMEM);

    /* Phase A */
    k_softmax<<<1, 64>>>(W1, W2);
    k_embed<<<512, 32>>>(emb);
    k_buildA<<<512, 256>>>(adj);
    k_Ls<<<512, 256>>>();
    dim3 g512(8, 8), b512(16, 16);
    k_gemm512<<<g512, b512>>>(pLs, pLs, (const float*)nullptr, pT2);
    k_gemm512<<<g512, b512>>>(pLs, pT2, pLs, pT3);
    dim3 gat(16, 16), bat(32, 8);
    k_att<<<gat, bat>>>(pLs, pATh + 0 * (size_t)NNODE * NNODE, pATl + 0 * (size_t)NNODE * NNODE);
    k_att<<<gat, bat>>>(pT2, pATh + 1 * (size_t)NNODE * NNODE, pATl + 1 * (size_t)NNODE * NNODE);
    k_att<<<gat, bat>>>(pT3, pATh + 2 * (size_t)NNODE * NNODE, pATl + 2 * (size_t)NNODE * NNODE);
    k_wid<<<16, 256>>>(mlpw);

    /* identity blocks -> out (non-accumulating write) */
    k_chanmix<<<NROWS / 64, 256>>>(x, pWid, 64, out);

    /* transpose+split x -> Zx */
    dim3 gx(24, 16, 32), bx(32, 8);
    k_xpose<<<gx, bx>>>(x, pZxh, pZxl);

    /* 3 chains of 3 hops each on HMMA tensor cores */
    dim3 gg(6, 4, 32);
    dim3 gc(8, 12, 32);
    for (int s = 0; s < 3; s++) {
        const __nv_bfloat16* ah = pATh + (size_t)s * NNODE * NNODE;
        const __nv_bfloat16* al = pATl + (size_t)s * NNODE * NNODE;
        k_node_gemm_mma<<<gg, 256, GEMM_SMEM>>>(pZxh, pZxl, ah, al, pZ1h, pZ1l);
        k_node_gemm_mma<<<gg, 256, GEMM_SMEM>>>(pZ1h, pZ1l, ah, al, pZ2h, pZ2l);
        k_node_gemm_mma<<<gg, 256, GEMM_SMEM>>>(pZ2h, pZ2l, ah, al, pZ3h, pZ3l);
        k_chanmix_chain<<<gc, 256>>>(pZ1h, pZ1l, pZ2h, pZ2l, pZ3h, pZ3l,
                                     mlpw, 4 + 3 * s, out, x, mlpb, s == 2 ? 1 : 0);
    }
}

// round 8
// speedup vs baseline: 2.5579x; 1.5610x over previous
#include <cuda_runtime.h>
#include <cuda_fp16.h>
#include <cstdint>
#include <cstddef>

#define NBATCH 32
#define NNODE  512
#define NTIME  12
#define NCH    64
#define NM     (NTIME * NCH)            /* 768 */
#define NROWS  (NBATCH * NNODE * NTIME) /* 196608 */
#define ZELEMS ((size_t)NBATCH * NM * NNODE) /* 12582912 */

/* ------------------------------------------------------------------ */
/* Device scratch                                                      */
/* ------------------------------------------------------------------ */
__device__ float g_SW1[40 * 20];
__device__ float g_SW2[40 * 20];
__device__ float g_e1[NNODE * 20];
__device__ float g_e2[NNODE * 20];
__device__ float g_A[NNODE * NNODE];
__device__ float g_dinv[NNODE];
__device__ float g_Ls[NNODE * NNODE];
__device__ float g_T2[NNODE * NNODE];
__device__ float g_T3[NNODE * NNODE];
__device__ float g_Wid[64 * 64];

__device__ __align__(1024) __half g_ATh[3][NNODE * NNODE];
__device__ __align__(1024) __half g_ATl[3][NNODE * NNODE];
__device__ __align__(1024) __half g_Zx[ZELEMS];
__device__ __align__(1024) __half g_Zall[9 * ZELEMS]; /* [hop*3+chain] */

/* ------------------------------------------------------------------ */
/* PTX helpers (plain compute_100-legal)                               */
/* ------------------------------------------------------------------ */
__device__ __forceinline__ uint32_t smem_to_u32(const void* p) {
    uint32_t a;
    asm("{ .reg .u64 t; cvta.to.shared.u64 t, %1; cvt.u32.u64 %0, t; }"
        : "=r"(a) : "l"(p));
    return a;
}
__device__ __forceinline__ void cpasync16(uint32_t s, const void* g) {
    asm volatile("cp.async.cg.shared.global [%0], [%1], 16;" :: "r"(s), "l"(g));
}
#define CP_COMMIT() asm volatile("cp.async.commit_group;" ::: "memory")
#define CP_WAIT1()  asm volatile("cp.async.wait_group 1;" ::: "memory")
#define CP_WAIT0()  asm volatile("cp.async.wait_group 0;" ::: "memory")

__device__ __forceinline__ void ldsm4(uint32_t& r0, uint32_t& r1,
                                      uint32_t& r2, uint32_t& r3, uint32_t a) {
    asm volatile("ldmatrix.sync.aligned.m8n8.x4.shared.b16 {%0,%1,%2,%3}, [%4];"
                 : "=r"(r0), "=r"(r1), "=r"(r2), "=r"(r3) : "r"(a));
}
__device__ __forceinline__ void mma16816f(float* c, const uint32_t* a,
                                          const uint32_t* b) {
    asm volatile(
        "mma.sync.aligned.m16n8k16.row.col.f32.f16.f16.f32 "
        "{%0,%1,%2,%3}, {%4,%5,%6,%7}, {%8,%9}, {%0,%1,%2,%3};"
        : "+f"(c[0]), "+f"(c[1]), "+f"(c[2]), "+f"(c[3])
        : "r"(a[0]), "r"(a[1]), "r"(a[2]), "r"(a[3]), "r"(b[0]), "r"(b[1]));
}

/* ------------------------------------------------------------------ */
/* Phase A (tiny, unchanged)                                           */
/* ------------------------------------------------------------------ */
__global__ void k_softmax(const float* __restrict__ W1,
                          const float* __restrict__ W2) {
    int j = threadIdx.x;
    if (j >= 40) return;
    const float* W = (j < 20) ? W1 : W2;
    float* S = (j < 20) ? g_SW1 : g_SW2;
    int col = (j < 20) ? j : (j - 20);
    float mx = -1e30f;
    for (int k = 0; k < 40; k++) mx = fmaxf(mx, W[k * 20 + col]);
    float s = 0.f;
    for (int k = 0; k < 40; k++) s += expf(W[k * 20 + col] - mx);
    float inv = 1.f / s;
    for (int k = 0; k < 40; k++) S[k * 20 + col] = expf(W[k * 20 + col] - mx) * inv;
}

__global__ void k_embed(const float* __restrict__ emb) {
    int row = blockIdx.x;
    int lane = threadIdx.x;
    float v1 = 0.f, v2 = 0.f;
    if (lane < 20) {
        for (int k = 0; k < 40; k++) {
            float e = emb[row * 40 + k];
            v1 += e * g_SW1[k * 20 + lane];
            v2 += e * g_SW2[k * 20 + lane];
        }
    }
    float n1 = v1 * v1, n2 = v2 * v2;
    for (int off = 16; off; off >>= 1) {
        n1 += __shfl_xor_sync(0xFFFFFFFFu, n1, off);
        n2 += __shfl_xor_sync(0xFFFFFFFFu, n2, off);
    }
    if (lane < 20) {
        g_e1[row * 20 + lane] = v1 / (sqrtf(n1) + 1e-8f);
        g_e2[row * 20 + lane] = v2 / (sqrtf(n2) + 1e-8f);
    }
}

__global__ void k_buildA(const float* __restrict__ adj) {
    int v = blockIdx.x;
    __shared__ float e1v[20];
    __shared__ float red[256];
    if (threadIdx.x < 20) e1v[threadIdx.x] = g_e1[v * 20 + threadIdx.x];
    __syncthreads();
    float sum = 0.f;
    for (int w = threadIdx.x; w < NNODE; w += 256) {
        float ad = adj[v * NNODE + w];
        float val = 9e-15f;
        if (ad > 0.f) {
            float dot = 0.f;
#pragma unroll
            for (int k = 0; k < 20; k++) dot += e1v[k] * g_e2[w * 20 + k];
            val = dot + ad;
        }
        g_A[v * NNODE + w] = val;
        sum += val;
    }
    red[threadIdx.x] = sum;
    __syncthreads();
    for (int s = 128; s; s >>= 1) {
        if (threadIdx.x < s) red[threadIdx.x] += red[threadIdx.x + s];
        __syncthreads();
    }
    if (threadIdx.x == 0) g_dinv[v] = 1.0f / sqrtf(red[0]);
}

__global__ void k_Ls() {
    int v = blockIdx.x;
    float dv = g_dinv[v];
    for (int w = threadIdx.x; w < NNODE; w += 256)
        g_Ls[v * NNODE + w] = -dv * g_A[v * NNODE + w] * g_dinv[w];
}

/* C = 2*A@B - (D ? D : I), 512x512 fp32 */
__global__ void k_gemm512(const float* __restrict__ A,
                          const float* __restrict__ B,
                          const float* __restrict__ D,
                          float* __restrict__ C) {
    __shared__ float As[16][68];
    __shared__ float Bs[16][68];
    const int tx = threadIdx.x, ty = threadIdx.y;
    const int t = ty * 16 + tx;
    const int i0 = blockIdx.y * 64, j0 = blockIdx.x * 64;
    float acc[4][4] = {};
    for (int k0 = 0; k0 < NNODE; k0 += 16) {
#pragma unroll
        for (int r = 0; r < 4; r++) {
            int idx = t + r * 256;
            int ia = idx >> 4, ka = idx & 15;
            As[ka][ia] = A[(size_t)(i0 + ia) * NNODE + k0 + ka];
            int kb = idx >> 6, jb = idx & 63;
            Bs[kb][jb] = B[(size_t)(k0 + kb) * NNODE + j0 + jb];
        }
        __syncthreads();
#pragma unroll
        for (int k = 0; k < 16; k++) {
            float av[4], bv[4];
#pragma unroll
            for (int i = 0; i < 4; i++) av[i] = As[k][ty * 4 + i];
#pragma unroll
            for (int j = 0; j < 4; j++) bv[j] = Bs[k][tx * 4 + j];
#pragma unroll
            for (int i = 0; i < 4; i++)
#pragma unroll
                for (int j = 0; j < 4; j++) acc[i][j] = fmaf(av[i], bv[j], acc[i][j]);
        }
        __syncthreads();
    }
#pragma unroll
    for (int i = 0; i < 4; i++)
#pragma unroll
        for (int j = 0; j < 4; j++) {
            int gi = i0 + ty * 4 + i, gj = j0 + tx * 4 + j;
            float sub = D ? D[(size_t)gi * NNODE + gj] : (gi == gj ? 1.f : 0.f);
            C[(size_t)gi * NNODE + gj] = 2.f * acc[i][j] - sub;
        }
}

__global__ void k_wid(const float* __restrict__ mlpw) {
    int i = blockIdx.x * 256 + threadIdx.x;
    int o = i >> 6, c = i & 63;
    g_Wid[i] = mlpw[o * 832 + c] + mlpw[o * 832 + 64 + c] +
               mlpw[o * 832 + 128 + c] + mlpw[o * 832 + 192 + c];
}

/* AT[w][v] = S[v][w], split to fp16 hi/lo */
__global__ void k_att(const float* __restrict__ S,
                      __half* __restrict__ Th,
                      __half* __restrict__ Tl) {
    __shared__ float tile[32][33];
    int w0 = blockIdx.x * 32, v0 = blockIdx.y * 32;
    int tx = threadIdx.x, ty = threadIdx.y;
#pragma unroll
    for (int i = 0; i < 4; i++)
        tile[ty + i * 8][tx] = S[(size_t)(v0 + ty + i * 8) * NNODE + w0 + tx];
    __syncthreads();
#pragma unroll
    for (int i = 0; i < 4; i++) {
        float val = tile[tx][ty + i * 8];
        size_t idx = (size_t)(w0 + ty + i * 8) * NNODE + v0 + tx;
        __half hi = __float2half(val);
        Th[idx] = hi;
        Tl[idx] = __float2half(val - __half2float(hi));
    }
}

/* Zx[b][m][v] = x[b][v][m], single fp16 */
__global__ void k_xpose(const float* __restrict__ x,
                        __half* __restrict__ Z) {
    __shared__ float tile[32][33];
    int m0 = blockIdx.x * 32, v0 = blockIdx.y * 32, b = blockIdx.z;
    int tx = threadIdx.x, ty = threadIdx.y;
#pragma unroll
    for (int i = 0; i < 4; i++)
        tile[ty + i * 8][tx] = x[((size_t)b * NNODE + v0 + ty + i * 8) * NM + m0 + tx];
    __syncthreads();
#pragma unroll
    for (int i = 0; i < 4; i++) {
        float val = tile[tx][ty + i * 8];
        size_t idx = ((size_t)b * NM + m0 + ty + i * 8) * NNODE + v0 + tx;
        Z[idx] = __float2half(val);
    }
}

/* ------------------------------------------------------------------ */
/* HMMA node GEMM (fp16 split-2): Y = Z * (Ah + Al), f32 accumulate    */
/* Zout[b][m][w] = sum_v Zin[b][m][v] * AT[w][v]                       */
/* Block 128x128, 8 warps (2m x 4n) of 64x32, BK=16                    */
/* 3-stage cp.async ring, one __syncthreads per iteration              */
/* All 3 chains batched: blockIdx.z = chain*32 + b                     */
/* ------------------------------------------------------------------ */
#define BKQ 16
#define ROWB 48                       /* 16 fp16 = 32 B data + 16 pad   */
#define MAT_BYTES (128 * ROWB)        /* 6144 */
#define STAGE_BYTES (3 * MAT_BYTES)   /* 18432: Z, ATh, ATl */
#define NSTAGE 3
#define GEMM_SMEM (NSTAGE * STAGE_BYTES) /* 55296 -> opt-in attribute   */

__global__ void __launch_bounds__(256, 2) k_node_gemm_mma(
    const __half* __restrict__ Zin, size_t zstride,
    const __half* __restrict__ AThb, const __half* __restrict__ ATlb,
    __half* __restrict__ Zoutb) {
    extern __shared__ __align__(128) char smem[];
    const uint32_t sb = smem_to_u32(smem);
    const int tid = threadIdx.x, wid = tid >> 5, lane = tid & 31;
    const int m0 = blockIdx.x * 128;
    const int w0 = blockIdx.y * 128;
    const int chain = blockIdx.z >> 5;
    const int b = blockIdx.z & 31;
    const __half* Zc = Zin + (size_t)chain * zstride;
    const __half* ATh = AThb + (size_t)chain * NNODE * NNODE;
    const __half* ATl = ATlb + (size_t)chain * NNODE * NNODE;
    __half* Zout = Zoutb + (size_t)chain * ZELEMS;
    const size_t zbase = ((size_t)b * NM + m0) * NNODE;
    const int warp_m = wid & 1;
    const int warp_n = wid >> 1;

    float acc[4][4][4];
#pragma unroll
    for (int i = 0; i < 4; i++)
#pragma unroll
        for (int j = 0; j < 4; j++)
#pragma unroll
            for (int k = 0; k < 4; k++) acc[i][j][k] = 0.f;

    /* stage loader: 768 cp.async of 16B = 3 per thread                 */
    auto load_stage = [&](int it, int s) {
        const int k0 = it * BKQ;
        const uint32_t sbase = sb + s * STAGE_BYTES;
#pragma unroll
        for (int i = 0; i < 3; i++) {
            int c = tid + i * 256;           /* 0..767 */
            int mat = c >> 8;                /* 0:Z 1:ATh 2:ATl */
            int cm = c & 255;
            int row = cm >> 1;
            int h = cm & 1;
            uint32_t dst = sbase + mat * MAT_BYTES + row * ROWB + h * 16;
            const __half* src;
            if (mat == 0)      src = Zc + zbase + (size_t)row * NNODE + k0 + h * 8;
            else if (mat == 1) src = ATh + (size_t)(w0 + row) * NNODE + k0 + h * 8;
            else               src = ATl + (size_t)(w0 + row) * NNODE + k0 + h * 8;
            cpasync16(dst, src);
        }
    };

    load_stage(0, 0);
    CP_COMMIT();
    load_stage(1, 1);
    CP_COMMIT();

    const uint32_t lrow = lane & 15;
    const uint32_t lhalf = (uint32_t)(lane >> 4) * 16;
    const int NIT = NNODE / BKQ; /* 32 */

    for (int it = 0; it < NIT; it++) {
        if (it < NIT - 1) CP_WAIT1(); else CP_WAIT0();
        __syncthreads();
        if (it + 2 < NIT) {
            load_stage(it + 2, (it + 2) % NSTAGE);
            CP_COMMIT();
        }

        const uint32_t sbase = sb + (it % NSTAGE) * STAGE_BYTES;
        uint32_t z[4][4], bh[4][2], bl[4][2];
#pragma unroll
        for (int mt = 0; mt < 4; mt++) {
            uint32_t a = sbase + (warp_m * 64 + mt * 16 + lrow) * ROWB + lhalf;
            ldsm4(z[mt][0], z[mt][1], z[mt][2], z[mt][3], a);
        }
#pragma unroll
        for (int nh = 0; nh < 2; nh++) {
            uint32_t a = sbase + MAT_BYTES +
                         (warp_n * 32 + nh * 16 + lrow) * ROWB + lhalf;
            uint32_t r0, r1, r2, r3;
            ldsm4(r0, r1, r2, r3, a);
            bh[nh * 2][0] = r0; bh[nh * 2][1] = r2;
            bh[nh * 2 + 1][0] = r1; bh[nh * 2 + 1][1] = r3;
            ldsm4(r0, r1, r2, r3, a + MAT_BYTES);
            bl[nh * 2][0] = r0; bl[nh * 2][1] = r2;
            bl[nh * 2 + 1][0] = r1; bl[nh * 2 + 1][1] = r3;
        }
#pragma unroll
        for (int mt = 0; mt < 4; mt++)
#pragma unroll
            for (int nt = 0; nt < 4; nt++) {
                mma16816f(acc[mt][nt], z[mt], bh[nt]);
                mma16816f(acc[mt][nt], z[mt], bl[nt]);
            }
    }

    /* epilogue: single fp16 output */
    const int qr = lane >> 2;
    const int qc = (lane & 3) * 2;
#pragma unroll
    for (int mt = 0; mt < 4; mt++) {
#pragma unroll
        for (int nt = 0; nt < 4; nt++) {
            const int row0 = m0 + warp_m * 64 + mt * 16 + qr;
            const int col = w0 + warp_n * 32 + nt * 8 + qc;
            const float* c = acc[mt][nt];
            size_t i0 = ((size_t)b * NM + row0) * NNODE + col;
            size_t i1 = i0 + (size_t)8 * NNODE;
            *(__half2*)(Zout + i0) = __floats2half2_rn(c[0], c[1]);
            *(__half2*)(Zout + i1) = __floats2half2_rn(c[2], c[3]);
        }
    }
}

/* ------------------------------------------------------------------ */
/* Unified epilogue: identity (fp32 x) + 9 hop blocks (fp16 Z) +       */
/* bias + residual + relu, single out write                            */
/* grid (8 wblk, 12 t, 32 b), 256 threads                              */
/* ------------------------------------------------------------------ */
__global__ void __launch_bounds__(256) k_epilogue(
    const float* __restrict__ x, const __half* __restrict__ Zall,
    const float* __restrict__ mlpw, const float* __restrict__ bias,
    float* __restrict__ out) {
    __shared__ float Ws[64][65];
    __shared__ float Ys[64][65];
    const int wblk = blockIdx.x;
    const int t = blockIdx.y;
    const int b = blockIdx.z;
    const int tid = threadIdx.x, tx = tid & 15, ty = tid >> 4;
    float acc[4][4] = {};

    /* pass 0: identity block from fp32 x (exact) with g_Wid */
    {
        for (int i = tid; i < 4096; i += 256) {
            int o = i >> 6, c = i & 63;
            Ws[c][o] = g_Wid[o * 64 + c];
        }
        for (int i = tid; i < 4096; i += 256) {
            int wp = i >> 6, c = i & 63;
            Ys[c][wp] = x[((size_t)(b * NNODE + wblk * 64 + wp) * NTIME + t) * 64 + c];
        }
        __syncthreads();
#pragma unroll
        for (int c = 0; c < 64; c++) {
            float yv[4], wv[4];
#pragma unroll
            for (int i = 0; i < 4; i++) yv[i] = Ys[c][ty * 4 + i];
#pragma unroll
            for (int j = 0; j < 4; j++) wv[j] = Ws[c][tx * 4 + j];
#pragma unroll
            for (int i = 0; i < 4; i++)
#pragma unroll
                for (int j = 0; j < 4; j++) acc[i][j] = fmaf(yv[i], wv[j], acc[i][j]);
        }
        __syncthreads();
    }

    /* passes 1..9: hop blocks from fp16 Z */
#pragma unroll 1
    for (int zi = 0; zi < 9; zi++) {
        const int hop = zi / 3, chain = zi % 3;
        const int coloff = (4 + 3 * chain + hop) * 64;
        const __half* Z = Zall + (size_t)zi * ZELEMS;
        for (int i = tid; i < 4096; i += 256) {
            int o = i >> 6, c = i & 63;
            Ws[c][o] = mlpw[(size_t)o * 832 + coloff + c];
        }
        for (int i = tid; i < 2048; i += 256) {
            int c = i >> 5, p = i & 31;
            size_t idx = ((size_t)b * NM + t * 64 + c) * NNODE + wblk * 64 + p * 2;
            __half2 v = *(const __half2*)(Z + idx);
            float2 f = __half22float2(v);
            Ys[c][p * 2] = f.x;
            Ys[c][p * 2 + 1] = f.y;
        }
        __syncthreads();
#pragma unroll
        for (int c = 0; c < 64; c++) {
            float yv[4], wv[4];
#pragma unroll
            for (int i = 0; i < 4; i++) yv[i] = Ys[c][ty * 4 + i];
#pragma unroll
            for (int j = 0; j < 4; j++) wv[j] = Ws[c][tx * 4 + j];
#pragma unroll
            for (int i = 0; i < 4; i++)
#pragma unroll
                for (int j = 0; j < 4; j++) acc[i][j] = fmaf(yv[i], wv[j], acc[i][j]);
        }
        __syncthreads();
    }

    /* write: bias + residual + relu, no RMW */
#pragma unroll
    for (int i = 0; i < 4; i++) {
        size_t r = ((size_t)(b * NNODE + wblk * 64 + ty * 4 + i) * NTIME + t);
        float* po = out + r * 64 + tx * 4;
        const float4 bb = *(const float4*)(bias + tx * 4);
        const float4 xo = *(const float4*)(x + r * 64 + tx * 4);
        float4 v;
        v.x = fmaxf(acc[i][0] + bb.x + xo.x, 0.f);
        v.y = fmaxf(acc[i][1] + bb.y + xo.y, 0.f);
        v.z = fmaxf(acc[i][2] + bb.z + xo.z, 0.f);
        v.w = fmaxf(acc[i][3] + bb.w + xo.w, 0.f);
        *(float4*)po = v;
    }
}

/* ------------------------------------------------------------------ */
extern "C" void kernel_launch(void* const* d_in, const int* in_sizes, int n_in,
                              void* d_out, int out_size) {
    (void)in_sizes; (void)n_in; (void)out_size;
    const float* x    = (const float*)d_in[0];
    const float* adj  = (const float*)d_in[1];
    const float* emb  = (const float*)d_in[2];
    const float* W1   = (const float*)d_in[3];
    const float* W2   = (const float*)d_in[4];
    const float* mlpw = (const float*)d_in[5];
    const float* mlpb = (const float*)d_in[6];
    float* out = (float*)d_out;

    float *pLs, *pT2, *pT3;
    __half *pATh, *pATl, *pZx, *pZall;
    cudaGetSymbolAddress((void**)&pLs, g_Ls);
    cudaGetSymbolAddress((void**)&pT2, g_T2);
    cudaGetSymbolAddress((void**)&pT3, g_T3);
    cudaGetSymbolAddress((void**)&pATh, g_ATh);
    cudaGetSymbolAddress((void**)&pATl, g_ATl);
    cudaGetSymbolAddress((void**)&pZx, g_Zx);
    cudaGetSymbolAddress((void**)&pZall, g_Zall);

    cudaFuncSetAttribute(k_node_gemm_mma,
                         cudaFuncAttributeMaxDynamicSharedMemorySize, GEMM_SMEM);

    /* Phase A */
    k_softmax<<<1, 64>>>(W1, W2);
    k_embed<<<512, 32>>>(emb);
    k_buildA<<<512, 256>>>(adj);
    k_Ls<<<512, 256>>>();
    dim3 g512(8, 8), b512(16, 16);
    k_gemm512<<<g512, b512>>>(pLs, pLs, (const float*)nullptr, pT2);
    k_gemm512<<<g512, b512>>>(pLs, pT2, pLs, pT3);
    dim3 gat(16, 16), bat(32, 8);
    const size_t NN = (size_t)NNODE * NNODE;
    k_att<<<gat, bat>>>(pLs, pATh + 0 * NN, pATl + 0 * NN);
    k_att<<<gat, bat>>>(pT2, pATh + 1 * NN, pATl + 1 * NN);
    k_att<<<gat, bat>>>(pT3, pATh + 2 * NN, pATl + 2 * NN);
    k_wid<<<16, 256>>>(mlpw);

    /* transpose x -> Zx (fp16) */
    dim3 gx(24, 16, 32), bx(32, 8);
    k_xpose<<<gx, bx>>>(x, pZx);

    /* 3 hops, all chains batched per launch */
    dim3 gg(6, 4, 96);
    k_node_gemm_mma<<<gg, 256, GEMM_SMEM>>>(pZx, (size_t)0, pATh, pATl,
                                            pZall + 0 * 3 * ZELEMS);
    k_node_gemm_mma<<<gg, 256, GEMM_SMEM>>>(pZall + 0 * 3 * ZELEMS, ZELEMS,
                                            pATh, pATl, pZall + 1 * 3 * ZELEMS);
    k_node_gemm_mma<<<gg, 256, GEMM_SMEM>>>(pZall + 1 * 3 * ZELEMS, ZELEMS,
                                            pATh, pATl, pZall + 2 * 3 * ZELEMS);

    /* fused epilogue */
    dim3 ge(8, 12, 32);
    k_epilogue<<<ge, 256>>>(x, pZall, mlpw, mlpb, out);
}

// round 9
// speedup vs baseline: 2.5641x; 1.0024x over previous
#include <cuda_runtime.h>
#include <cuda_fp16.h>
#include <cstdint>
#include <cstddef>

#define NBATCH 32
#define NNODE  512
#define NTIME  12
#define NCH    64
#define NM     (NTIME * NCH)            /* 768 */
#define NROWS  (NBATCH * NNODE * NTIME) /* 196608 */
#define ZELEMS ((size_t)NBATCH * NM * NNODE) /* 12582912 */

/* ------------------------------------------------------------------ */
/* Device scratch                                                      */
/* ------------------------------------------------------------------ */
__device__ float g_SW1[40 * 20];
__device__ float g_SW2[40 * 20];
__device__ float g_e1[NNODE * 20];
__device__ float g_e2[NNODE * 20];
__device__ float g_A[NNODE * NNODE];
__device__ float g_dinv[NNODE];
__device__ float g_Ls[NNODE * NNODE];
__device__ float g_T2[NNODE * NNODE];
__device__ float g_T3[NNODE * NNODE];
__device__ float g_Wid[64 * 64];

__device__ __align__(1024) __half g_ATh[3][NNODE * NNODE];
__device__ __align__(1024) __half g_ATl[3][NNODE * NNODE];
__device__ __align__(1024) __half g_Zx[ZELEMS];
__device__ __align__(1024) __half g_Zall[9 * ZELEMS]; /* [hop*3+chain] */

/* ------------------------------------------------------------------ */
/* PTX helpers (plain compute_100-legal)                               */
/* ------------------------------------------------------------------ */
__device__ __forceinline__ uint32_t smem_to_u32(const void* p) {
    uint32_t a;
    asm("{ .reg .u64 t; cvta.to.shared.u64 t, %1; cvt.u32.u64 %0, t; }"
        : "=r"(a) : "l"(p));
    return a;
}
__device__ __forceinline__ void cpasync16(uint32_t s, const void* g) {
    asm volatile("cp.async.cg.shared.global [%0], [%1], 16;" :: "r"(s), "l"(g));
}
#define CP_COMMIT() asm volatile("cp.async.commit_group;" ::: "memory")
#define CP_WAIT1()  asm volatile("cp.async.wait_group 1;" ::: "memory")
#define CP_WAIT0()  asm volatile("cp.async.wait_group 0;" ::: "memory")

__device__ __forceinline__ void ldsm4(uint32_t& r0, uint32_t& r1,
                                      uint32_t& r2, uint32_t& r3, uint32_t a) {
    asm volatile("ldmatrix.sync.aligned.m8n8.x4.shared.b16 {%0,%1,%2,%3}, [%4];"
                 : "=r"(r0), "=r"(r1), "=r"(r2), "=r"(r3) : "r"(a));
}
__device__ __forceinline__ void mma16816f(float* c, const uint32_t* a,
                                          const uint32_t* b) {
    asm volatile(
        "mma.sync.aligned.m16n8k16.row.col.f32.f16.f16.f32 "
        "{%0,%1,%2,%3}, {%4,%5,%6,%7}, {%8,%9}, {%0,%1,%2,%3};"
        : "+f"(c[0]), "+f"(c[1]), "+f"(c[2]), "+f"(c[3])
        : "r"(a[0]), "r"(a[1]), "r"(a[2]), "r"(a[3]), "r"(b[0]), "r"(b[1]));
}

/* ------------------------------------------------------------------ */
/* Phase A (tiny, unchanged)                                           */
/* ------------------------------------------------------------------ */
__global__ void k_softmax(const float* __restrict__ W1,
                          const float* __restrict__ W2) {
    int j = threadIdx.x;
    if (j >= 40) return;
    const float* W = (j < 20) ? W1 : W2;
    float* S = (j < 20) ? g_SW1 : g_SW2;
    int col = (j < 20) ? j : (j - 20);
    float mx = -1e30f;
    for (int k = 0; k < 40; k++) mx = fmaxf(mx, W[k * 20 + col]);
    float s = 0.f;
    for (int k = 0; k < 40; k++) s += expf(W[k * 20 + col] - mx);
    float inv = 1.f / s;
    for (int k = 0; k < 40; k++) S[k * 20 + col] = expf(W[k * 20 + col] - mx) * inv;
}

__global__ void k_embed(const float* __restrict__ emb) {
    int row = blockIdx.x;
    int lane = threadIdx.x;
    float v1 = 0.f, v2 = 0.f;
    if (lane < 20) {
        for (int k = 0; k < 40; k++) {
            float e = emb[row * 40 + k];
            v1 += e * g_SW1[k * 20 + lane];
            v2 += e * g_SW2[k * 20 + lane];
        }
    }
    float n1 = v1 * v1, n2 = v2 * v2;
    for (int off = 16; off; off >>= 1) {
        n1 += __shfl_xor_sync(0xFFFFFFFFu, n1, off);
        n2 += __shfl_xor_sync(0xFFFFFFFFu, n2, off);
    }
    if (lane < 20) {
        g_e1[row * 20 + lane] = v1 / (sqrtf(n1) + 1e-8f);
        g_e2[row * 20 + lane] = v2 / (sqrtf(n2) + 1e-8f);
    }
}

__global__ void k_buildA(const float* __restrict__ adj) {
    int v = blockIdx.x;
    __shared__ float e1v[20];
    __shared__ float red[256];
    if (threadIdx.x < 20) e1v[threadIdx.x] = g_e1[v * 20 + threadIdx.x];
    __syncthreads();
    float sum = 0.f;
    for (int w = threadIdx.x; w < NNODE; w += 256) {
        float ad = adj[v * NNODE + w];
        float val = 9e-15f;
        if (ad > 0.f) {
            float dot = 0.f;
#pragma unroll
            for (int k = 0; k < 20; k++) dot += e1v[k] * g_e2[w * 20 + k];
            val = dot + ad;
        }
        g_A[v * NNODE + w] = val;
        sum += val;
    }
    red[threadIdx.x] = sum;
    __syncthreads();
    for (int s = 128; s; s >>= 1) {
        if (threadIdx.x < s) red[threadIdx.x] += red[threadIdx.x + s];
        __syncthreads();
    }
    if (threadIdx.x == 0) g_dinv[v] = 1.0f / sqrtf(red[0]);
}

__global__ void k_Ls() {
    int v = blockIdx.x;
    float dv = g_dinv[v];
    for (int w = threadIdx.x; w < NNODE; w += 256)
        g_Ls[v * NNODE + w] = -dv * g_A[v * NNODE + w] * g_dinv[w];
}

/* C = 2*A@B - (D ? D : I), 512x512 fp32 */
__global__ void k_gemm512(const float* __restrict__ A,
                          const float* __restrict__ B,
                          const float* __restrict__ D,
                          float* __restrict__ C) {
    __shared__ float As[16][68];
    __shared__ float Bs[16][68];
    const int tx = threadIdx.x, ty = threadIdx.y;
    const int t = ty * 16 + tx;
    const int i0 = blockIdx.y * 64, j0 = blockIdx.x * 64;
    float acc[4][4] = {};
    for (int k0 = 0; k0 < NNODE; k0 += 16) {
#pragma unroll
        for (int r = 0; r < 4; r++) {
            int idx = t + r * 256;
            int ia = idx >> 4, ka = idx & 15;
            As[ka][ia] = A[(size_t)(i0 + ia) * NNODE + k0 + ka];
            int kb = idx >> 6, jb = idx & 63;
            Bs[kb][jb] = B[(size_t)(k0 + kb) * NNODE + j0 + jb];
        }
        __syncthreads();
#pragma unroll
        for (int k = 0; k < 16; k++) {
            float av[4], bv[4];
#pragma unroll
            for (int i = 0; i < 4; i++) av[i] = As[k][ty * 4 + i];
#pragma unroll
            for (int j = 0; j < 4; j++) bv[j] = Bs[k][tx * 4 + j];
#pragma unroll
            for (int i = 0; i < 4; i++)
#pragma unroll
                for (int j = 0; j < 4; j++) acc[i][j] = fmaf(av[i], bv[j], acc[i][j]);
        }
        __syncthreads();
    }
#pragma unroll
    for (int i = 0; i < 4; i++)
#pragma unroll
        for (int j = 0; j < 4; j++) {
            int gi = i0 + ty * 4 + i, gj = j0 + tx * 4 + j;
            float sub = D ? D[(size_t)gi * NNODE + gj] : (gi == gj ? 1.f : 0.f);
            C[(size_t)gi * NNODE + gj] = 2.f * acc[i][j] - sub;
        }
}

__global__ void k_wid(const float* __restrict__ mlpw) {
    int i = blockIdx.x * 256 + threadIdx.x;
    int o = i >> 6, c = i & 63;
    g_Wid[i] = mlpw[o * 832 + c] + mlpw[o * 832 + 64 + c] +
               mlpw[o * 832 + 128 + c] + mlpw[o * 832 + 192 + c];
}

/* AT[w][v] = S[v][w], split to fp16 hi/lo */
__global__ void k_att(const float* __restrict__ S,
                      __half* __restrict__ Th,
                      __half* __restrict__ Tl) {
    __shared__ float tile[32][33];
    int w0 = blockIdx.x * 32, v0 = blockIdx.y * 32;
    int tx = threadIdx.x, ty = threadIdx.y;
#pragma unroll
    for (int i = 0; i < 4; i++)
        tile[ty + i * 8][tx] = S[(size_t)(v0 + ty + i * 8) * NNODE + w0 + tx];
    __syncthreads();
#pragma unroll
    for (int i = 0; i < 4; i++) {
        float val = tile[tx][ty + i * 8];
        size_t idx = (size_t)(w0 + ty + i * 8) * NNODE + v0 + tx;
        __half hi = __float2half(val);
        Th[idx] = hi;
        Tl[idx] = __float2half(val - __half2float(hi));
    }
}

/* Zx[b][m][v] = x[b][v][m], single fp16 */
__global__ void k_xpose(const float* __restrict__ x,
                        __half* __restrict__ Z) {
    __shared__ float tile[32][33];
    int m0 = blockIdx.x * 32, v0 = blockIdx.y * 32, b = blockIdx.z;
    int tx = threadIdx.x, ty = threadIdx.y;
#pragma unroll
    for (int i = 0; i < 4; i++)
        tile[ty + i * 8][tx] = x[((size_t)b * NNODE + v0 + ty + i * 8) * NM + m0 + tx];
    __syncthreads();
#pragma unroll
    for (int i = 0; i < 4; i++) {
        float val = tile[tx][ty + i * 8];
        size_t idx = ((size_t)b * NM + m0 + ty + i * 8) * NNODE + v0 + tx;
        Z[idx] = __float2half(val);
    }
}

/* ------------------------------------------------------------------ */
/* HMMA node GEMM (fp16 split-2): Y = Z * (Ah + Al), f32 accumulate    */
/* Zout[b][m][w] = sum_v Zin[b][m][v] * AT[w][v]                       */
/* Block 128x128, 8 warps (2m x 4n) of 64x32, BK=16                    */
/* 3-stage cp.async ring, one __syncthreads per iteration              */
/* All 3 chains batched: blockIdx.z = chain*32 + b                     */
/* ------------------------------------------------------------------ */
#define BKQ 16
#define ROWB 48                       /* 16 fp16 = 32 B data + 16 pad   */
#define MAT_BYTES (128 * ROWB)        /* 6144 */
#define STAGE_BYTES (3 * MAT_BYTES)   /* 18432: Z, ATh, ATl */
#define NSTAGE 3
#define GEMM_SMEM (NSTAGE * STAGE_BYTES) /* 55296 -> opt-in attribute   */

__global__ void __launch_bounds__(256, 2) k_node_gemm_mma(
    const __half* __restrict__ Zin, size_t zstride,
    const __half* __restrict__ AThb, const __half* __restrict__ ATlb,
    __half* __restrict__ Zoutb) {
    extern __shared__ __align__(128) char smem[];
    const uint32_t sb = smem_to_u32(smem);
    const int tid = threadIdx.x, wid = tid >> 5, lane = tid & 31;
    const int m0 = blockIdx.x * 128;
    const int w0 = blockIdx.y * 128;
    const int chain = blockIdx.z >> 5;
    const int b = blockIdx.z & 31;
    const __half* Zc = Zin + (size_t)chain * zstride;
    const __half* ATh = AThb + (size_t)chain * NNODE * NNODE;
    const __half* ATl = ATlb + (size_t)chain * NNODE * NNODE;
    __half* Zout = Zoutb + (size_t)chain * ZELEMS;
    const size_t zbase = ((size_t)b * NM + m0) * NNODE;
    const int warp_m = wid & 1;
    const int warp_n = wid >> 1;

    float acc[4][4][4];
#pragma unroll
    for (int i = 0; i < 4; i++)
#pragma unroll
        for (int j = 0; j < 4; j++)
#pragma unroll
            for (int k = 0; k < 4; k++) acc[i][j][k] = 0.f;

    /* stage loader: 768 cp.async of 16B = 3 per thread                 */
    auto load_stage = [&](int it, int s) {
        const int k0 = it * BKQ;
        const uint32_t sbase = sb + s * STAGE_BYTES;
#pragma unroll
        for (int i = 0; i < 3; i++) {
            int c = tid + i * 256;           /* 0..767 */
            int mat = c >> 8;                /* 0:Z 1:ATh 2:ATl */
            int cm = c & 255;
            int row = cm >> 1;
            int h = cm & 1;
            uint32_t dst = sbase + mat * MAT_BYTES + row * ROWB + h * 16;
            const __half* src;
            if (mat == 0)      src = Zc + zbase + (size_t)row * NNODE + k0 + h * 8;
            else if (mat == 1) src = ATh + (size_t)(w0 + row) * NNODE + k0 + h * 8;
            else               src = ATl + (size_t)(w0 + row) * NNODE + k0 + h * 8;
            cpasync16(dst, src);
        }
    };

    load_stage(0, 0);
    CP_COMMIT();
    load_stage(1, 1);
    CP_COMMIT();

    const uint32_t lrow = lane & 15;
    const uint32_t lhalf = (uint32_t)(lane >> 4) * 16;
    const int NIT = NNODE / BKQ; /* 32 */

    for (int it = 0; it < NIT; it++) {
        if (it < NIT - 1) CP_WAIT1(); else CP_WAIT0();
        __syncthreads();
        if (it + 2 < NIT) {
            load_stage(it + 2, (it + 2) % NSTAGE);
            CP_COMMIT();
        }

        const uint32_t sbase = sb + (it % NSTAGE) * STAGE_BYTES;
        uint32_t z[4][4], bh[4][2], bl[4][2];
#pragma unroll
        for (int mt = 0; mt < 4; mt++) {
            uint32_t a = sbase + (warp_m * 64 + mt * 16 + lrow) * ROWB + lhalf;
            ldsm4(z[mt][0], z[mt][1], z[mt][2], z[mt][3], a);
        }
#pragma unroll
        for (int nh = 0; nh < 2; nh++) {
            uint32_t a = sbase + MAT_BYTES +
                         (warp_n * 32 + nh * 16 + lrow) * ROWB + lhalf;
            uint32_t r0, r1, r2, r3;
            ldsm4(r0, r1, r2, r3, a);
            bh[nh * 2][0] = r0; bh[nh * 2][1] = r2;
            bh[nh * 2 + 1][0] = r1; bh[nh * 2 + 1][1] = r3;
            ldsm4(r0, r1, r2, r3, a + MAT_BYTES);
            bl[nh * 2][0] = r0; bl[nh * 2][1] = r2;
            bl[nh * 2 + 1][0] = r1; bl[nh * 2 + 1][1] = r3;
        }
#pragma unroll
        for (int mt = 0; mt < 4; mt++)
#pragma unroll
            for (int nt = 0; nt < 4; nt++) {
                mma16816f(acc[mt][nt], z[mt], bh[nt]);
                mma16816f(acc[mt][nt], z[mt], bl[nt]);
            }
    }

    /* epilogue: single fp16 output */
    const int qr = lane >> 2;
    const int qc = (lane & 3) * 2;
#pragma unroll
    for (int mt = 0; mt < 4; mt++) {
#pragma unroll
        for (int nt = 0; nt < 4; nt++) {
            const int row0 = m0 + warp_m * 64 + mt * 16 + qr;
            const int col = w0 + warp_n * 32 + nt * 8 + qc;
            const float* c = acc[mt][nt];
            size_t i0 = ((size_t)b * NM + row0) * NNODE + col;
            size_t i1 = i0 + (size_t)8 * NNODE;
            *(__half2*)(Zout + i0) = __floats2half2_rn(c[0], c[1]);
            *(__half2*)(Zout + i1) = __floats2half2_rn(c[2], c[3]);
        }
    }
}

/* ------------------------------------------------------------------ */
/* Unified epilogue: identity (fp32 x) + 9 hop blocks (fp16 Z) +       */
/* bias + residual + relu, single out write                            */
/* grid (8 wblk, 12 t, 32 b), 256 threads                              */
/* ------------------------------------------------------------------ */
__global__ void __launch_bounds__(256) k_epilogue(
    const float* __restrict__ x, const __half* __restrict__ Zall,
    const float* __restrict__ mlpw, const float* __restrict__ bias,
    float* __restrict__ out) {
    __shared__ float Ws[64][65];
    __shared__ float Ys[64][65];
    const int wblk = blockIdx.x;
    const int t = blockIdx.y;
    const int b = blockIdx.z;
    const int tid = threadIdx.x, tx = tid & 15, ty = tid >> 4;
    float acc[4][4] = {};

    /* pass 0: identity block from fp32 x (exact) with g_Wid */
    {
        for (int i = tid; i < 4096; i += 256) {
            int o = i >> 6, c = i & 63;
            Ws[c][o] = g_Wid[o * 64 + c];
        }
        for (int i = tid; i < 4096; i += 256) {
            int wp = i >> 6, c = i & 63;
            Ys[c][wp] = x[((size_t)(b * NNODE + wblk * 64 + wp) * NTIME + t) * 64 + c];
        }
        __syncthreads();
#pragma unroll
        for (int c = 0; c < 64; c++) {
            float yv[4], wv[4];
#pragma unroll
            for (int i = 0; i < 4; i++) yv[i] = Ys[c][ty * 4 + i];
#pragma unroll
            for (int j = 0; j < 4; j++) wv[j] = Ws[c][tx * 4 + j];
#pragma unroll
            for (int i = 0; i < 4; i++)
#pragma unroll
                for (int j = 0; j < 4; j++) acc[i][j] = fmaf(yv[i], wv[j], acc[i][j]);
        }
        __syncthreads();
    }

    /* passes 1..9: hop blocks from fp16 Z */
#pragma unroll 1
    for (int zi = 0; zi < 9; zi++) {
        const int hop = zi / 3, chain = zi % 3;
        const int coloff = (4 + 3 * chain + hop) * 64;
        const __half* Z = Zall + (size_t)zi * ZELEMS;
        for (int i = tid; i < 4096; i += 256) {
            int o = i >> 6, c = i & 63;
            Ws[c][o] = mlpw[(size_t)o * 832 + coloff + c];
        }
        for (int i = tid; i < 2048; i += 256) {
            int c = i >> 5, p = i & 31;
            size_t idx = ((size_t)b * NM + t * 64 + c) * NNODE + wblk * 64 + p * 2;
            __half2 v = *(const __half2*)(Z + idx);
            float2 f = __half22float2(v);
            Ys[c][p * 2] = f.x;
            Ys[c][p * 2 + 1] = f.y;
        }
        __syncthreads();
#pragma unroll
        for (int c = 0; c < 64; c++) {
            float yv[4], wv[4];
#pragma unroll
            for (int i = 0; i < 4; i++) yv[i] = Ys[c][ty * 4 + i];
#pragma unroll
            for (int j = 0; j < 4; j++) wv[j] = Ws[c][tx * 4 + j];
#pragma unroll
            for (int i = 0; i < 4; i++)
#pragma unroll
                for (int j = 0; j < 4; j++) acc[i][j] = fmaf(yv[i], wv[j], acc[i][j]);
        }
        __syncthreads();
    }

    /* write: bias + residual + relu, no RMW */
#pragma unroll
    for (int i = 0; i < 4; i++) {
        size_t r = ((size_t)(b * NNODE + wblk * 64 + ty * 4 + i) * NTIME + t);
        float* po = out + r * 64 + tx * 4;
        const float4 bb = *(const float4*)(bias + tx * 4);
        const float4 xo = *(const float4*)(x + r * 64 + tx * 4);
        float4 v;
        v.x = fmaxf(acc[i][0] + bb.x + xo.x, 0.f);
        v.y = fmaxf(acc[i][1] + bb.y + xo.y, 0.f);
        v.z = fmaxf(acc[i][2] + bb.z + xo.z, 0.f);
        v.w = fmaxf(acc[i][3] + bb.w + xo.w, 0.f);
        *(float4*)po = v;
    }
}

/* ------------------------------------------------------------------ */
extern "C" void kernel_launch(void* const* d_in, const int* in_sizes, int n_in,
                              void* d_out, int out_size) {
    (void)in_sizes; (void)n_in; (void)out_size;
    const float* x    = (const float*)d_in[0];
    const float* adj  = (const float*)d_in[1];
    const float* emb  = (const float*)d_in[2];
    const float* W1   = (const float*)d_in[3];
    const float* W2   = (const float*)d_in[4];
    const float* mlpw = (const float*)d_in[5];
    const float* mlpb = (const float*)d_in[6];
    float* out = (float*)d_out;

    float *pLs, *pT2, *pT3;
    __half *pATh, *pATl, *pZx, *pZall;
    cudaGetSymbolAddress((void**)&pLs, g_Ls);
    cudaGetSymbolAddress((void**)&pT2, g_T2);
    cudaGetSymbolAddress((void**)&pT3, g_T3);
    cudaGetSymbolAddress((void**)&pATh, g_ATh);
    cudaGetSymbolAddress((void**)&pATl, g_ATl);
    cudaGetSymbolAddress((void**)&pZx, g_Zx);
    cudaGetSymbolAddress((void**)&pZall, g_Zall);

    cudaFuncSetAttribute(k_node_gemm_mma,
                         cudaFuncAttributeMaxDynamicSharedMemorySize, GEMM_SMEM);

    /* Phase A */
    k_softmax<<<1, 64>>>(W1, W2);
    k_embed<<<512, 32>>>(emb);
    k_buildA<<<512, 256>>>(adj);
    k_Ls<<<512, 256>>>();
    dim3 g512(8, 8), b512(16, 16);
    k_gemm512<<<g512, b512>>>(pLs, pLs, (const float*)nullptr, pT2);
    k_gemm512<<<g512, b512>>>(pLs, pT2, pLs, pT3);
    dim3 gat(16, 16), bat(32, 8);
    const size_t NN = (size_t)NNODE * NNODE;
    k_att<<<gat, bat>>>(pLs, pATh + 0 * NN, pATl + 0 * NN);
    k_att<<<gat, bat>>>(pT2, pATh + 1 * NN, pATl + 1 * NN);
    k_att<<<gat, bat>>>(pT3, pATh + 2 * NN, pATl + 2 * NN);
    k_wid<<<16, 256>>>(mlpw);

    /* transpose x -> Zx (fp16) */
    dim3 gx(24, 16, 32), bx(32, 8);
    k_xpose<<<gx, bx>>>(x, pZx);

    /* 3 hops, all chains batched per launch */
    dim3 gg(6, 4, 96);
    k_node_gemm_mma<<<gg, 256, GEMM_SMEM>>>(pZx, (size_t)0, pATh, pATl,
                                            pZall + 0 * 3 * ZELEMS);
    k_node_gemm_mma<<<gg, 256, GEMM_SMEM>>>(pZall + 0 * 3 * ZELEMS, ZELEMS,
                                            pATh, pATl, pZall + 1 * 3 * ZELEMS);
    k_node_gemm_mma<<<gg, 256, GEMM_SMEM>>>(pZall + 1 * 3 * ZELEMS, ZELEMS,
                                            pATh, pATl, pZall + 2 * 3 * ZELEMS);

    /* fused epilogue */
    dim3 ge(8, 12, 32);
    k_epilogue<<<ge, 256>>>(x, pZall, mlpw, mlpb, out);
}

// round 10
// speedup vs baseline: 3.4130x; 1.3311x over previous
#include <cuda_runtime.h>
#include <cuda_fp16.h>
#include <cstdint>
#include <cstddef>

#define NBATCH 32
#define NNODE  512
#define NTIME  12
#define NCH    64
#define NM     (NTIME * NCH)            /* 768 */
#define NROWS  (NBATCH * NNODE * NTIME) /* 196608 */
#define ZELEMS ((size_t)NBATCH * NM * NNODE) /* 12582912 */
#define NN     ((size_t)NNODE * NNODE)

/* ------------------------------------------------------------------ */
/* Device scratch                                                      */
/* ------------------------------------------------------------------ */
__device__ float g_SW1[40 * 20];
__device__ float g_SW2[40 * 20];
__device__ float g_e1[NNODE * 20];
__device__ float g_e2[NNODE * 20];
__device__ float g_A[NNODE * NNODE];
__device__ float g_dinv[NNODE];
__device__ float g_Ls[NNODE * NNODE];
__device__ float g_T2[NNODE * NNODE];
__device__ float g_T3[NNODE * NNODE];
__device__ float g_P2[3][NNODE * NNODE];  /* S_s^2, fp32 */
__device__ float g_P3[3][NNODE * NNODE];  /* S_s^3, fp32 */
__device__ float g_Wid[64 * 64];

/* 9 transposed operators in fp16: op = s*3 + (p-1) */
__device__ __align__(1024) __half g_OPT[9][NNODE * NNODE];
__device__ __align__(1024) __half g_Zx[ZELEMS];
__device__ __align__(1024) __half g_Zall[9 * ZELEMS];

/* ------------------------------------------------------------------ */
/* PTX helpers (plain compute_100-legal)                               */
/* ------------------------------------------------------------------ */
__device__ __forceinline__ uint32_t smem_to_u32(const void* p) {
    uint32_t a;
    asm("{ .reg .u64 t; cvta.to.shared.u64 t, %1; cvt.u32.u64 %0, t; }"
        : "=r"(a) : "l"(p));
    return a;
}
__device__ __forceinline__ void cpasync16(uint32_t s, const void* g) {
    asm volatile("cp.async.cg.shared.global [%0], [%1], 16;" :: "r"(s), "l"(g));
}
#define CP_COMMIT() asm volatile("cp.async.commit_group;" ::: "memory")
#define CP_WAIT1()  asm volatile("cp.async.wait_group 1;" ::: "memory")
#define CP_WAIT0()  asm volatile("cp.async.wait_group 0;" ::: "memory")

__device__ __forceinline__ void ldsm4(uint32_t& r0, uint32_t& r1,
                                      uint32_t& r2, uint32_t& r3, uint32_t a) {
    asm volatile("ldmatrix.sync.aligned.m8n8.x4.shared.b16 {%0,%1,%2,%3}, [%4];"
                 : "=r"(r0), "=r"(r1), "=r"(r2), "=r"(r3) : "r"(a));
}
__device__ __forceinline__ void mma16816f(float* c, const uint32_t* a,
                                          const uint32_t* b) {
    asm volatile(
        "mma.sync.aligned.m16n8k16.row.col.f32.f16.f16.f32 "
        "{%0,%1,%2,%3}, {%4,%5,%6,%7}, {%8,%9}, {%0,%1,%2,%3};"
        : "+f"(c[0]), "+f"(c[1]), "+f"(c[2]), "+f"(c[3])
        : "r"(a[0]), "r"(a[1]), "r"(a[2]), "r"(a[3]), "r"(b[0]), "r"(b[1]));
}

/* ------------------------------------------------------------------ */
/* Phase A (tiny)                                                      */
/* ------------------------------------------------------------------ */
__global__ void k_softmax(const float* __restrict__ W1,
                          const float* __restrict__ W2) {
    int j = threadIdx.x;
    if (j >= 40) return;
    const float* W = (j < 20) ? W1 : W2;
    float* S = (j < 20) ? g_SW1 : g_SW2;
    int col = (j < 20) ? j : (j - 20);
    float mx = -1e30f;
    for (int k = 0; k < 40; k++) mx = fmaxf(mx, W[k * 20 + col]);
    float s = 0.f;
    for (int k = 0; k < 40; k++) s += expf(W[k * 20 + col] - mx);
    float inv = 1.f / s;
    for (int k = 0; k < 40; k++) S[k * 20 + col] = expf(W[k * 20 + col] - mx) * inv;
}

__global__ void k_embed(const float* __restrict__ emb) {
    int row = blockIdx.x;
    int lane = threadIdx.x;
    float v1 = 0.f, v2 = 0.f;
    if (lane < 20) {
        for (int k = 0; k < 40; k++) {
            float e = emb[row * 40 + k];
            v1 += e * g_SW1[k * 20 + lane];
            v2 += e * g_SW2[k * 20 + lane];
        }
    }
    float n1 = v1 * v1, n2 = v2 * v2;
    for (int off = 16; off; off >>= 1) {
        n1 += __shfl_xor_sync(0xFFFFFFFFu, n1, off);
        n2 += __shfl_xor_sync(0xFFFFFFFFu, n2, off);
    }
    if (lane < 20) {
        g_e1[row * 20 + lane] = v1 / (sqrtf(n1) + 1e-8f);
        g_e2[row * 20 + lane] = v2 / (sqrtf(n2) + 1e-8f);
    }
}

__global__ void k_buildA(const float* __restrict__ adj) {
    int v = blockIdx.x;
    __shared__ float e1v[20];
    __shared__ float red[256];
    if (threadIdx.x < 20) e1v[threadIdx.x] = g_e1[v * 20 + threadIdx.x];
    __syncthreads();
    float sum = 0.f;
    for (int w = threadIdx.x; w < NNODE; w += 256) {
        float ad = adj[v * NNODE + w];
        float val = 9e-15f;
        if (ad > 0.f) {
            float dot = 0.f;
#pragma unroll
            for (int k = 0; k < 20; k++) dot += e1v[k] * g_e2[w * 20 + k];
            val = dot + ad;
        }
        g_A[v * NNODE + w] = val;
        sum += val;
    }
    red[threadIdx.x] = sum;
    __syncthreads();
    for (int s = 128; s; s >>= 1) {
        if (threadIdx.x < s) red[threadIdx.x] += red[threadIdx.x + s];
        __syncthreads();
    }
    if (threadIdx.x == 0) g_dinv[v] = 1.0f / sqrtf(red[0]);
}

__global__ void k_Ls() {
    int v = blockIdx.x;
    float dv = g_dinv[v];
    for (int w = threadIdx.x; w < NNODE; w += 256)
        g_Ls[v * NNODE + w] = -dv * g_A[v * NNODE + w] * g_dinv[w];
}

/* C = 2*A@B - (D ? D : I), 512x512 fp32 */
__global__ void k_gemm512(const float* __restrict__ A,
                          const float* __restrict__ B,
                          const float* __restrict__ D,
                          float* __restrict__ C) {
    __shared__ float As[16][68];
    __shared__ float Bs[16][68];
    const int tx = threadIdx.x, ty = threadIdx.y;
    const int t = ty * 16 + tx;
    const int i0 = blockIdx.y * 64, j0 = blockIdx.x * 64;
    float acc[4][4] = {};
    for (int k0 = 0; k0 < NNODE; k0 += 16) {
#pragma unroll
        for (int r = 0; r < 4; r++) {
            int idx = t + r * 256;
            int ia = idx >> 4, ka = idx & 15;
            As[ka][ia] = A[(size_t)(i0 + ia) * NNODE + k0 + ka];
            int kb = idx >> 6, jb = idx & 63;
            Bs[kb][jb] = B[(size_t)(k0 + kb) * NNODE + j0 + jb];
        }
        __syncthreads();
#pragma unroll
        for (int k = 0; k < 16; k++) {
            float av[4], bv[4];
#pragma unroll
            for (int i = 0; i < 4; i++) av[i] = As[k][ty * 4 + i];
#pragma unroll
            for (int j = 0; j < 4; j++) bv[j] = Bs[k][tx * 4 + j];
#pragma unroll
            for (int i = 0; i < 4; i++)
#pragma unroll
                for (int j = 0; j < 4; j++) acc[i][j] = fmaf(av[i], bv[j], acc[i][j]);
        }
        __syncthreads();
    }
#pragma unroll
    for (int i = 0; i < 4; i++)
#pragma unroll
        for (int j = 0; j < 4; j++) {
            int gi = i0 + ty * 4 + i, gj = j0 + tx * 4 + j;
            float sub = D ? D[(size_t)gi * NNODE + gj] : (gi == gj ? 1.f : 0.f);
            C[(size_t)gi * NNODE + gj] = 2.f * acc[i][j] - sub;
        }
}

/* Plain power GEMM, batched over 3 chains: mode 0: P2[s]=S_s@S_s,
   mode 1: P3[s]=S_s@P2[s]. */
__global__ void k_gemm512p(int mode, float* __restrict__ P2b,
                           float* __restrict__ P3b) {
    __shared__ float As[16][68];
    __shared__ float Bs[16][68];
    const int s = blockIdx.z;
    const float* S = (s == 0) ? g_Ls : (s == 1) ? g_T2 : g_T3;
    const float* A = S;
    const float* B = (mode == 0) ? S : (P2b + (size_t)s * NN);
    float* C = (mode == 0) ? (P2b + (size_t)s * NN) : (P3b + (size_t)s * NN);
    const int tx = threadIdx.x, ty = threadIdx.y;
    const int t = ty * 16 + tx;
    const int i0 = blockIdx.y * 64, j0 = blockIdx.x * 64;
    float acc[4][4] = {};
    for (int k0 = 0; k0 < NNODE; k0 += 16) {
#pragma unroll
        for (int r = 0; r < 4; r++) {
            int idx = t + r * 256;
            int ia = idx >> 4, ka = idx & 15;
            As[ka][ia] = A[(size_t)(i0 + ia) * NNODE + k0 + ka];
            int kb = idx >> 6, jb = idx & 63;
            Bs[kb][jb] = B[(size_t)(k0 + kb) * NNODE + j0 + jb];
        }
        __syncthreads();
#pragma unroll
        for (int k = 0; k < 16; k++) {
            float av[4], bv[4];
#pragma unroll
            for (int i = 0; i < 4; i++) av[i] = As[k][ty * 4 + i];
#pragma unroll
            for (int j = 0; j < 4; j++) bv[j] = Bs[k][tx * 4 + j];
#pragma unroll
            for (int i = 0; i < 4; i++)
#pragma unroll
                for (int j = 0; j < 4; j++) acc[i][j] = fmaf(av[i], bv[j], acc[i][j]);
        }
        __syncthreads();
    }
#pragma unroll
    for (int i = 0; i < 4; i++)
#pragma unroll
        for (int j = 0; j < 4; j++)
            C[(size_t)(i0 + ty * 4 + i) * NNODE + j0 + tx * 4 + j] = acc[i][j];
}

__global__ void k_wid(const float* __restrict__ mlpw) {
    int i = blockIdx.x * 256 + threadIdx.x;
    int o = i >> 6, c = i & 63;
    g_Wid[i] = mlpw[o * 832 + c] + mlpw[o * 832 + 64 + c] +
               mlpw[o * 832 + 128 + c] + mlpw[o * 832 + 192 + c];
}

/* OPT[op][w][v] = (A_s^p)[v][w] fp16, op = s*3 + (p-1) */
__global__ void k_att9() {
    __shared__ float tile[32][33];
    const int op = blockIdx.z;
    const int s = op / 3, p = op % 3; /* p: 0->S, 1->S^2, 2->S^3 */
    const float* S;
    if (p == 0) S = (s == 0) ? g_Ls : (s == 1) ? g_T2 : g_T3;
    else if (p == 1) S = g_P2[s];
    else S = g_P3[s];
    __half* T = g_OPT[op];
    int w0 = blockIdx.x * 32, v0 = blockIdx.y * 32;
    int tx = threadIdx.x, ty = threadIdx.y;
#pragma unroll
    for (int i = 0; i < 4; i++)
        tile[ty + i * 8][tx] = S[(size_t)(v0 + ty + i * 8) * NNODE + w0 + tx];
    __syncthreads();
#pragma unroll
    for (int i = 0; i < 4; i++) {
        size_t idx = (size_t)(w0 + ty + i * 8) * NNODE + v0 + tx;
        T[idx] = __float2half(tile[tx][ty + i * 8]);
    }
}

/* Zx[b][m][v] = x[b][v][m], single fp16 */
__global__ void k_xpose(const float* __restrict__ x,
                        __half* __restrict__ Z) {
    __shared__ float tile[32][33];
    int m0 = blockIdx.x * 32, v0 = blockIdx.y * 32, b = blockIdx.z;
    int tx = threadIdx.x, ty = threadIdx.y;
#pragma unroll
    for (int i = 0; i < 4; i++)
        tile[ty + i * 8][tx] = x[((size_t)b * NNODE + v0 + ty + i * 8) * NM + m0 + tx];
    __syncthreads();
#pragma unroll
    for (int i = 0; i < 4; i++) {
        float val = tile[tx][ty + i * 8];
        size_t idx = ((size_t)b * NM + m0 + ty + i * 8) * NNODE + v0 + tx;
        Z[idx] = __float2half(val);
    }
}

/* ------------------------------------------------------------------ */
/* HMMA node GEMM (fp16, single product): Zall[op] = Zx * OPT[op]      */
/* Block 128x128, 8 warps (2m x 4n) of 64x32, BK=16                    */
/* 3-stage cp.async ring, one __syncthreads per iteration              */
/* blockIdx.z = op*32 + b, all 9 operators in ONE launch               */
/* ------------------------------------------------------------------ */
#define BKQ 16
#define ROWB 48                       /* 16 fp16 = 32 B data + 16 pad   */
#define MAT_BYTES (128 * ROWB)        /* 6144 */
#define STAGE_BYTES (2 * MAT_BYTES)   /* 12288: Z, AT */
#define NSTAGE 3
#define GEMM_SMEM (NSTAGE * STAGE_BYTES) /* 36864 < 48KB */

__global__ void __launch_bounds__(256, 2) k_node_gemm_mma(
    const __half* __restrict__ Zx, const __half* __restrict__ OPTb,
    __half* __restrict__ Zallb) {
    extern __shared__ __align__(128) char smem[];
    const uint32_t sb = smem_to_u32(smem);
    const int tid = threadIdx.x, wid = tid >> 5, lane = tid & 31;
    const int m0 = blockIdx.x * 128;
    const int w0 = blockIdx.y * 128;
    const int op = blockIdx.z >> 5;
    const int b = blockIdx.z & 31;
    const __half* AT = OPTb + (size_t)op * NN;
    __half* Zout = Zallb + (size_t)op * ZELEMS;
    const size_t zbase = ((size_t)b * NM + m0) * NNODE;
    const int warp_m = wid & 1;
    const int warp_n = wid >> 1;

    float acc[4][4][4];
#pragma unroll
    for (int i = 0; i < 4; i++)
#pragma unroll
        for (int j = 0; j < 4; j++)
#pragma unroll
            for (int k = 0; k < 4; k++) acc[i][j][k] = 0.f;

    /* stage loader: 512 cp.async of 16B = 2 per thread                 */
    auto load_stage = [&](int it, int s) {
        const int k0 = it * BKQ;
        const uint32_t sbase = sb + s * STAGE_BYTES;
#pragma unroll
        for (int i = 0; i < 2; i++) {
            int c = tid + i * 256;           /* 0..511 */
            int mat = c >> 8;                /* 0:Z 1:AT */
            int cm = c & 255;
            int row = cm >> 1;
            int h = cm & 1;
            uint32_t dst = sbase + mat * MAT_BYTES + row * ROWB + h * 16;
            const __half* src = (mat == 0)
                ? (Zx + zbase + (size_t)row * NNODE + k0 + h * 8)
                : (AT + (size_t)(w0 + row) * NNODE + k0 + h * 8);
            cpasync16(dst, src);
        }
    };

    load_stage(0, 0);
    CP_COMMIT();
    load_stage(1, 1);
    CP_COMMIT();

    const uint32_t lrow = lane & 15;
    const uint32_t lhalf = (uint32_t)(lane >> 4) * 16;
    const int NIT = NNODE / BKQ; /* 32 */

    for (int it = 0; it < NIT; it++) {
        if (it < NIT - 1) CP_WAIT1(); else CP_WAIT0();
        __syncthreads();
        if (it + 2 < NIT) {
            load_stage(it + 2, (it + 2) % NSTAGE);
            CP_COMMIT();
        }

        const uint32_t sbase = sb + (it % NSTAGE) * STAGE_BYTES;
        uint32_t z[4][4], bq[4][2];
#pragma unroll
        for (int mt = 0; mt < 4; mt++) {
            uint32_t a = sbase + (warp_m * 64 + mt * 16 + lrow) * ROWB + lhalf;
            ldsm4(z[mt][0], z[mt][1], z[mt][2], z[mt][3], a);
        }
#pragma unroll
        for (int nh = 0; nh < 2; nh++) {
            uint32_t a = sbase + MAT_BYTES +
                         (warp_n * 32 + nh * 16 + lrow) * ROWB + lhalf;
            uint32_t r0, r1, r2, r3;
            ldsm4(r0, r1, r2, r3, a);
            bq[nh * 2][0] = r0; bq[nh * 2][1] = r2;
            bq[nh * 2 + 1][0] = r1; bq[nh * 2 + 1][1] = r3;
        }
#pragma unroll
        for (int mt = 0; mt < 4; mt++)
#pragma unroll
            for (int nt = 0; nt < 4; nt++)
                mma16816f(acc[mt][nt], z[mt], bq[nt]);
    }

    /* epilogue: single fp16 output */
    const int qr = lane >> 2;
    const int qc = (lane & 3) * 2;
#pragma unroll
    for (int mt = 0; mt < 4; mt++) {
#pragma unroll
        for (int nt = 0; nt < 4; nt++) {
            const int row0 = m0 + warp_m * 64 + mt * 16 + qr;
            const int col = w0 + warp_n * 32 + nt * 8 + qc;
            const float* c = acc[mt][nt];
            size_t i0 = ((size_t)b * NM + row0) * NNODE + col;
            size_t i1 = i0 + (size_t)8 * NNODE;
            *(__half2*)(Zout + i0) = __floats2half2_rn(c[0], c[1]);
            *(__half2*)(Zout + i1) = __floats2half2_rn(c[2], c[3]);
        }
    }
}

/* ------------------------------------------------------------------ */
/* Unified epilogue: identity (fp32 x) + 9 blocks (fp16 Z) +           */
/* bias + residual + relu, single out write                            */
/* ------------------------------------------------------------------ */
__global__ void __launch_bounds__(256) k_epilogue(
    const float* __restrict__ x, const __half* __restrict__ Zall,
    const float* __restrict__ mlpw, const float* __restrict__ bias,
    float* __restrict__ out) {
    __shared__ float Ws[64][65];
    __shared__ float Ys[64][65];
    const int wblk = blockIdx.x;
    const int t = blockIdx.y;
    const int b = blockIdx.z;
    const int tid = threadIdx.x, tx = tid & 15, ty = tid >> 4;
    float acc[4][4] = {};

    /* pass 0: identity block from fp32 x (exact) with g_Wid */
    {
        for (int i = tid; i < 4096; i += 256) {
            int o = i >> 6, c = i & 63;
            Ws[c][o] = g_Wid[o * 64 + c];
        }
        for (int i = tid; i < 4096; i += 256) {
            int wp = i >> 6, c = i & 63;
            Ys[c][wp] = x[((size_t)(b * NNODE + wblk * 64 + wp) * NTIME + t) * 64 + c];
        }
        __syncthreads();
#pragma unroll
        for (int c = 0; c < 64; c++) {
            float yv[4], wv[4];
#pragma unroll
            for (int i = 0; i < 4; i++) yv[i] = Ys[c][ty * 4 + i];
#pragma unroll
            for (int j = 0; j < 4; j++) wv[j] = Ws[c][tx * 4 + j];
#pragma unroll
            for (int i = 0; i < 4; i++)
#pragma unroll
                for (int j = 0; j < 4; j++) acc[i][j] = fmaf(yv[i], wv[j], acc[i][j]);
        }
        __syncthreads();
    }

    /* passes: 9 blocks; zi = s*3 + (p-1) -> mlp block 4 + 3s + (p-1)   */
#pragma unroll 1
    for (int zi = 0; zi < 9; zi++) {
        const int s = zi / 3, hop = zi % 3;
        const int coloff = (4 + 3 * s + hop) * 64;
        const __half* Z = Zall + (size_t)zi * ZELEMS;
        for (int i = tid; i < 4096; i += 256) {
            int o = i >> 6, c = i & 63;
            Ws[c][o] = mlpw[(size_t)o * 832 + coloff + c];
        }
        for (int i = tid; i < 2048; i += 256) {
            int c = i >> 5, p = i & 31;
            size_t idx = ((size_t)b * NM + t * 64 + c) * NNODE + wblk * 64 + p * 2;
            __half2 v = *(const __half2*)(Z + idx);
            float2 f = __half22float2(v);
            Ys[c][p * 2] = f.x;
            Ys[c][p * 2 + 1] = f.y;
        }
        __syncthreads();
#pragma unroll
        for (int c = 0; c < 64; c++) {
            float yv[4], wv[4];
#pragma unroll
            for (int i = 0; i < 4; i++) yv[i] = Ys[c][ty * 4 + i];
#pragma unroll
            for (int j = 0; j < 4; j++) wv[j] = Ws[c][tx * 4 + j];
#pragma unroll
            for (int i = 0; i < 4; i++)
#pragma unroll
                for (int j = 0; j < 4; j++) acc[i][j] = fmaf(yv[i], wv[j], acc[i][j]);
        }
        __syncthreads();
    }

    /* write: bias + residual + relu, no RMW */
#pragma unroll
    for (int i = 0; i < 4; i++) {
        size_t r = ((size_t)(b * NNODE + wblk * 64 + ty * 4 + i) * NTIME + t);
        float* po = out + r * 64 + tx * 4;
        const float4 bb = *(const float4*)(bias + tx * 4);
        const float4 xo = *(const float4*)(x + r * 64 + tx * 4);
        float4 v;
        v.x = fmaxf(acc[i][0] + bb.x + xo.x, 0.f);
        v.y = fmaxf(acc[i][1] + bb.y + xo.y, 0.f);
        v.z = fmaxf(acc[i][2] + bb.z + xo.z, 0.f);
        v.w = fmaxf(acc[i][3] + bb.w + xo.w, 0.f);
        *(float4*)po = v;
    }
}

/* ------------------------------------------------------------------ */
extern "C" void kernel_launch(void* const* d_in, const int* in_sizes, int n_in,
                              void* d_out, int out_size) {
    (void)in_sizes; (void)n_in; (void)out_size;
    const float* x    = (const float*)d_in[0];
    const float* adj  = (const float*)d_in[1];
    const float* emb  = (const float*)d_in[2];
    const float* W1   = (const float*)d_in[3];
    const float* W2   = (const float*)d_in[4];
    const float* mlpw = (const float*)d_in[5];
    const float* mlpb = (const float*)d_in[6];
    float* out = (float*)d_out;

    float *pLs, *pT2, *pT3, *pP2, *pP3;
    __half *pOPT, *pZx, *pZall;
    cudaGetSymbolAddress((void**)&pLs, g_Ls);
    cudaGetSymbolAddress((void**)&pT2, g_T2);
    cudaGetSymbolAddress((void**)&pT3, g_T3);
    cudaGetSymbolAddress((void**)&pP2, g_P2);
    cudaGetSymbolAddress((void**)&pP3, g_P3);
    cudaGetSymbolAddress((void**)&pOPT, g_OPT);
    cudaGetSymbolAddress((void**)&pZx, g_Zx);
    cudaGetSymbolAddress((void**)&pZall, g_Zall);

    /* Phase A: supports + powers */
    k_softmax<<<1, 64>>>(W1, W2);
    k_embed<<<512, 32>>>(emb);
    k_buildA<<<512, 256>>>(adj);
    k_Ls<<<512, 256>>>();
    dim3 g512(8, 8), b512(16, 16);
    k_gemm512<<<g512, b512>>>(pLs, pLs, (const float*)nullptr, pT2);
    k_gemm512<<<g512, b512>>>(pLs, pT2, pLs, pT3);
    dim3 gp(8, 8, 3);
    k_gemm512p<<<gp, b512>>>(0, pP2, pP3);  /* P2[s] = S_s^2 */
    k_gemm512p<<<gp, b512>>>(1, pP2, pP3);  /* P3[s] = S_s^3 */
    dim3 ga9(16, 16, 9), bat(32, 8);
    k_att9<<<ga9, bat>>>();
    k_wid<<<16, 256>>>(mlpw);

    /* transpose x -> Zx (fp16, rounded ONCE) */
    dim3 gx(24, 16, 32), bx(32, 8);
    k_xpose<<<gx, bx>>>(x, pZx);

    /* all 9 node GEMMs in one launch, no serial dependency */
    dim3 gg(6, 4, 288);
    k_node_gemm_mma<<<gg, 256, GEMM_SMEM>>>(pZx, pOPT, pZall);

    /* fused epilogue */
    dim3 ge(8, 12, 32);
    k_epilogue<<<ge, 256>>>(x, pZall, mlpw, mlpb, out);
}